// round 11
// baseline (speedup 1.0000x reference)
#include <cuda_runtime.h>
#include <cuda_bf16.h>
#include <math.h>
#include <stdint.h>

// Problem constants
#define BATCH 64
#define TT    1024
#define DIN   64
#define HID   128
#define G3    384   // 3*HID
#define D2    256   // 2*HID
#define MROWS (BATCH*TT)   // 65536

typedef unsigned long long ull;

// ---------------- f32x2 packed helpers (sm_103a FFMA2) ----------------------
__device__ __forceinline__ ull fma2(ull a, ull b, ull c) {
    ull d;
    asm("fma.rn.f32x2 %0, %1, %2, %3;" : "=l"(d) : "l"(a), "l"(b), "l"(c));
    return d;
}
__device__ __forceinline__ float2 unpack2(ull v) {
    float2 r;
    asm("mov.b64 {%0, %1}, %2;" : "=f"(r.x), "=f"(r.y) : "l"(v));
    return r;
}
__device__ __forceinline__ float sigm(float x) {
    return 1.f / (1.f + __expf(-x));
}
__device__ __forceinline__ float ftanh(float x) {
    return __fmaf_rn(2.f, 1.f / (1.f + __expf(-2.f * x)), -1.f);
}

// ---------------- bf16 HMMA (m16n8k16) --------------------------------------
__device__ __forceinline__ void mma_bf16(float* c,
                                         uint32_t a0, uint32_t a1, uint32_t a2, uint32_t a3,
                                         uint32_t b0, uint32_t b1) {
    asm volatile(
        "mma.sync.aligned.m16n8k16.row.col.f32.bf16.bf16.f32 "
        "{%0,%1,%2,%3}, {%4,%5,%6,%7}, {%8,%9}, {%0,%1,%2,%3};"
        : "+f"(c[0]), "+f"(c[1]), "+f"(c[2]), "+f"(c[3])
        : "r"(a0), "r"(a1), "r"(a2), "r"(a3), "r"(b0), "r"(b1));
}

// ---------------- scratch (device globals; no allocation allowed) ----------
__device__ float g_xW[2][MROWS][G3];          // input projections per dir
__device__ float g_z1[MROWS][D2];             // layer-1 output (fp32 for attn)
__device__ __nv_bfloat16 g_xh[MROWS * DIN],  g_xl[MROWS * DIN];
__device__ __nv_bfloat16 g_z0h[MROWS * D2],  g_z0l[MROWS * D2];
__device__ __nv_bfloat16 g_w0h[2][G3 * DIN], g_w0l[2][G3 * DIN];
__device__ __nv_bfloat16 g_w1h[2][G3 * D2],  g_w1l[2][G3 * D2];

// ---------------- fused fp32 -> bf16 (hi, lo) split conversion -------------
#define XN  (MROWS * DIN)
#define W0N (G3 * DIN)
#define W1N (G3 * D2)
__global__ __launch_bounds__(256)
void convert_all_kernel(const float* __restrict__ x,
                        const float* __restrict__ w0f, const float* __restrict__ w0b,
                        const float* __restrict__ w1f, const float* __restrict__ w1b)
{
    const int total = XN + 2 * W0N + 2 * W1N;
    for (int i = blockIdx.x * 256 + threadIdx.x; i < total; i += gridDim.x * 256) {
        const float* src;
        __nv_bfloat16 *hi, *lo;
        int k = i;
        if (k < XN)                    { src = x;   hi = g_xh;     lo = g_xl;     }
        else if ((k -= XN) < W0N)      { src = w0f; hi = g_w0h[0]; lo = g_w0l[0]; }
        else if ((k -= W0N) < W0N)     { src = w0b; hi = g_w0h[1]; lo = g_w0l[1]; }
        else if ((k -= W0N) < W1N)     { src = w1f; hi = g_w1h[0]; lo = g_w1l[0]; }
        else      { k -= W1N;            src = w1b; hi = g_w1h[1]; lo = g_w1l[1]; }
        float v = src[k];
        __nv_bfloat16 h = __float2bfloat16(v);
        hi[k] = h;
        lo[k] = __float2bfloat16(v - __bfloat162float(h));
    }
}

// ---------------- HMMA projection GEMM (R10 — proven) -----------------------
#define LDP 40
__global__ __launch_bounds__(256, 1)
void mma_proj_kernel(const float* __restrict__ bf,  const float* __restrict__ bb,
                     const float* __restrict__ bhf, const float* __restrict__ bhb,
                     int K, int layer)
{
    __shared__ __align__(16) __nv_bfloat16 sAh[128][LDP];
    __shared__ __align__(16) __nv_bfloat16 sAl[128][LDP];
    __shared__ __align__(16) __nv_bfloat16 sWh[128][LDP];
    __shared__ __align__(16) __nv_bfloat16 sWl[128][LDP];
    __shared__ float sBias[128];

    const int tid  = threadIdx.x;
    const int wid  = tid >> 5;
    const int lane = tid & 31;
    const int g    = lane >> 2;
    const int tig  = lane & 3;
    const int wr   = wid >> 1;
    const int wc   = wid & 1;
    const int m0   = blockIdx.x * 128;
    const int n0   = blockIdx.y * 128;
    const int dir  = blockIdx.z;

    const __nv_bfloat16* __restrict__ Ah = layer ? g_z0h : g_xh;
    const __nv_bfloat16* __restrict__ Al = layer ? g_z0l : g_xl;
    const __nv_bfloat16* __restrict__ Wh = layer ? g_w1h[dir] : g_w0h[dir];
    const __nv_bfloat16* __restrict__ Wl = layer ? g_w1l[dir] : g_w0l[dir];
    const float* __restrict__ bias = dir ? bb : bf;
    const float* __restrict__ bhh  = dir ? bhb : bhf;

    if (tid < 128) {
        int c = n0 + tid;
        sBias[tid] = bias[c] + (c < 2 * HID ? bhh[c] : 0.f);
    }

    const int lr0 = tid >> 1;
    const int lc0 = (tid & 1) * 16;

    float acc[2][8][4];
    #pragma unroll
    for (int a = 0; a < 2; ++a)
        #pragma unroll
        for (int b = 0; b < 8; ++b)
            #pragma unroll
            for (int cc = 0; cc < 4; ++cc) acc[a][b][cc] = 0.f;

    const int nchunks = K >> 5;

    uint4 pAh0, pAh1, pAl0, pAl1, pWh0, pWh1, pWl0, pWl1;
    {
        const size_t ga = (size_t)(m0 + lr0) * K + lc0;
        const size_t gw = (size_t)(n0 + lr0) * K + lc0;
        pAh0 = *(const uint4*)(Ah + ga);     pAh1 = *(const uint4*)(Ah + ga + 8);
        pAl0 = *(const uint4*)(Al + ga);     pAl1 = *(const uint4*)(Al + ga + 8);
        pWh0 = *(const uint4*)(Wh + gw);     pWh1 = *(const uint4*)(Wh + gw + 8);
        pWl0 = *(const uint4*)(Wl + gw);     pWl1 = *(const uint4*)(Wl + gw + 8);
    }

    for (int c = 0; c < nchunks; ++c) {
        *(uint4*)&sAh[lr0][lc0] = pAh0;  *(uint4*)&sAh[lr0][lc0 + 8] = pAh1;
        *(uint4*)&sAl[lr0][lc0] = pAl0;  *(uint4*)&sAl[lr0][lc0 + 8] = pAl1;
        *(uint4*)&sWh[lr0][lc0] = pWh0;  *(uint4*)&sWh[lr0][lc0 + 8] = pWh1;
        *(uint4*)&sWl[lr0][lc0] = pWl0;  *(uint4*)&sWl[lr0][lc0 + 8] = pWl1;
        __syncthreads();

        if (c + 1 < nchunks) {
            const size_t ga = (size_t)(m0 + lr0) * K + (c + 1) * 32 + lc0;
            const size_t gw = (size_t)(n0 + lr0) * K + (c + 1) * 32 + lc0;
            pAh0 = *(const uint4*)(Ah + ga);  pAh1 = *(const uint4*)(Ah + ga + 8);
            pAl0 = *(const uint4*)(Al + ga);  pAl1 = *(const uint4*)(Al + ga + 8);
            pWh0 = *(const uint4*)(Wh + gw);  pWh1 = *(const uint4*)(Wh + gw + 8);
            pWl0 = *(const uint4*)(Wl + gw);  pWl1 = *(const uint4*)(Wl + gw + 8);
        }

        #pragma unroll
        for (int ks = 0; ks < 2; ++ks) {
            const int kc = ks * 16 + tig * 2;
            uint32_t ah[2][4], al[2][4];
            #pragma unroll
            for (int mt = 0; mt < 2; ++mt) {
                const int r = wr * 32 + mt * 16 + g;
                ah[mt][0] = *(const uint32_t*)&sAh[r][kc];
                ah[mt][1] = *(const uint32_t*)&sAh[r + 8][kc];
                ah[mt][2] = *(const uint32_t*)&sAh[r][kc + 8];
                ah[mt][3] = *(const uint32_t*)&sAh[r + 8][kc + 8];
                al[mt][0] = *(const uint32_t*)&sAl[r][kc];
                al[mt][1] = *(const uint32_t*)&sAl[r + 8][kc];
                al[mt][2] = *(const uint32_t*)&sAl[r][kc + 8];
                al[mt][3] = *(const uint32_t*)&sAl[r + 8][kc + 8];
            }
            #pragma unroll
            for (int nt = 0; nt < 8; ++nt) {
                const int wn = wc * 64 + nt * 8 + g;
                uint32_t bh0 = *(const uint32_t*)&sWh[wn][kc];
                uint32_t bh1 = *(const uint32_t*)&sWh[wn][kc + 8];
                uint32_t bl0 = *(const uint32_t*)&sWl[wn][kc];
                uint32_t bl1 = *(const uint32_t*)&sWl[wn][kc + 8];
                #pragma unroll
                for (int mt = 0; mt < 2; ++mt) {
                    mma_bf16(acc[mt][nt], ah[mt][0], ah[mt][1], ah[mt][2], ah[mt][3], bh0, bh1);
                    mma_bf16(acc[mt][nt], ah[mt][0], ah[mt][1], ah[mt][2], ah[mt][3], bl0, bl1);
                    mma_bf16(acc[mt][nt], al[mt][0], al[mt][1], al[mt][2], al[mt][3], bh0, bh1);
                }
            }
        }
        __syncthreads();
    }

    float* Cout = &g_xW[dir][0][0];
    #pragma unroll
    for (int mt = 0; mt < 2; ++mt) {
        const int mrow = m0 + wr * 32 + mt * 16 + g;
        #pragma unroll
        for (int nt = 0; nt < 8; ++nt) {
            const int ncol  = wc * 64 + nt * 8 + tig * 2;
            const int gcol  = n0 + ncol;
            float2 o0 = {acc[mt][nt][0] + sBias[ncol],
                         acc[mt][nt][1] + sBias[ncol + 1]};
            float2 o1 = {acc[mt][nt][2] + sBias[ncol],
                         acc[mt][nt][3] + sBias[ncol + 1]};
            *(float2*)(Cout + (size_t)mrow * G3 + gcol)       = o0;
            *(float2*)(Cout + (size_t)(mrow + 8) * G3 + gcol) = o1;
        }
    }
}

// ---------------- GRU recurrence — r/n colocated in warp --------------------
// 384 threads:
//   warps 0-7: lanes 0-15 = r-gate of o = w*16+(l&15); lanes 16-31 = n-gate of same o.
//   warps 8-11: z-gate of o = tid-256.
// After the dot: all lanes compute sigm; n-lanes get r via shfl (no smem, no bar),
// compute tanh BEFORE the barrier; z publishes via smem. Post-barrier tail is
// only: LDS z + blend + stores.
__global__ __launch_bounds__(384, 1)
void gru_scan_kernel(const float* __restrict__ whh_f, const float* __restrict__ whh_b,
                     const float* __restrict__ bhh_f, const float* __restrict__ bhh_b,
                     int layer)
{
    const int b   = blockIdx.x >> 1;
    const int dir = blockIdx.x & 1;
    const int tid = threadIdx.x;
    const int w   = tid >> 5;
    const int l   = tid & 31;

    const bool rn_warp = (w < 8);
    const int  o   = rn_warp ? (w * 16 + (l & 15)) : (tid - 256);
    const int  row = rn_warp ? ((l < 16) ? o : (2 * HID + o)) : (HID + o);
    const bool is_n = rn_warp && (l >= 16);
    const bool is_z = !rn_warp;

    const float* __restrict__ whh = dir ? whh_b : whh_f;
    const float* __restrict__ bhh = dir ? bhh_b : bhh_f;

    __shared__ __align__(16) float h_s[HID];
    __shared__ float z_s[HID];

    // load Whh row into 64 packed f32x2 registers
    ull w2[64];
    #pragma unroll
    for (int i = 0; i < 64; i += 2) {
        ulonglong2 v = *(const ulonglong2*)(whh + (size_t)row * HID + 2 * i);
        w2[i] = v.x; w2[i + 1] = v.y;
    }
    const float bj = is_n ? bhh[2 * HID + o] : 0.f;   // bhh_n stays inside r*(.)
    float hreg = 0.f;
    if (tid < HID) h_s[tid] = 0.f;

    const float* __restrict__ gi = &g_xW[dir][(size_t)b * TT][0];
    float* __restrict__ zf = &g_z1[(size_t)b * TT][0] + dir * HID;
    __nv_bfloat16* __restrict__ zh = g_z0h + (size_t)b * TT * D2 + dir * HID;
    __nv_bfloat16* __restrict__ zl = g_z0l + (size_t)b * TT * D2 + dir * HID;

    const int t0 = dir ? (TT - 1) : 0;
    float gi_v = __ldcs(gi + (size_t)t0 * G3 + row);
    __syncthreads();

    for (int t = 0; t < TT; ++t) {
        const int tt = dir ? (TT - 1 - t) : t;

        // prefetch NEXT step's gi
        float pre = 0.f;
        if (t + 1 < TT) {
            const int tn = dir ? (TT - 2 - t) : (t + 1);
            pre = __ldcs(gi + (size_t)tn * G3 + row);
        }

        // gh = Whh[row,:] . h  (packed FFMA2, explicit LDS staging)
        ull a0 = 0ull, a1 = 0ull;
        const ull* h2 = (const ull*)h_s;
        #pragma unroll
        for (int i = 0; i < 64; i += 8) {
            ulonglong2 hv0 = *(const ulonglong2*)(h2 + i);
            ulonglong2 hv1 = *(const ulonglong2*)(h2 + i + 2);
            ulonglong2 hv2 = *(const ulonglong2*)(h2 + i + 4);
            ulonglong2 hv3 = *(const ulonglong2*)(h2 + i + 6);
            a0 = fma2(w2[i],     hv0.x, a0);
            a1 = fma2(w2[i + 1], hv0.y, a1);
            a0 = fma2(w2[i + 2], hv1.x, a0);
            a1 = fma2(w2[i + 3], hv1.y, a1);
            a0 = fma2(w2[i + 4], hv2.x, a0);
            a1 = fma2(w2[i + 5], hv2.y, a1);
            a0 = fma2(w2[i + 6], hv3.x, a0);
            a1 = fma2(w2[i + 7], hv3.y, a1);
        }
        float2 s0 = unpack2(a0), s1 = unpack2(a1);
        float gh = (s0.x + s0.y) + (s1.x + s1.y);

        // all lanes: sigmoid (r,z meaningful; n-lanes produce harmless garbage)
        float sg = sigm(gi_v + gh);
        // n-lanes fetch r from lane (l&15); r-lanes read their own value
        float rr = __shfl_sync(0xffffffffu, sg, l & 15);

        float nv = 0.f;
        if (rn_warp) {
            // valid in n-lanes (bj = 0, rr = own sg in r-lanes: finite, unused)
            nv = ftanh(gi_v + rr * (gh + bj));
        }
        if (is_z) z_s[o] = sg;
        __syncthreads();                        // z published, h reads done

        if (is_n) {
            float zg = z_s[o];
            hreg = (1.f - zg) * nv + zg * hreg;
            h_s[o] = hreg;
            if (layer) {
                zf[(size_t)tt * D2 + o] = hreg;
            } else {
                __nv_bfloat16 hi = __float2bfloat16(hreg);
                zh[(size_t)tt * D2 + o] = hi;
                zl[(size_t)tt * D2 + o] = __float2bfloat16(hreg - __bfloat162float(hi));
            }
        }
        gi_v = pre;
        __syncthreads();                        // h ready for next dot
    }
}

// ---------------- attention pooling + heads (512 threads) ------------------
__global__ __launch_bounds__(512)
void attn_head_kernel(const float* __restrict__ attn_w, const float* __restrict__ attn_b,
                      const float* __restrict__ motor_w, const float* __restrict__ motor_b,
                      const float* __restrict__ state_w, const float* __restrict__ state_b,
                      const int* __restrict__ motor_k, float* __restrict__ out)
{
    const int b = blockIdx.x;
    const int tid = threadIdx.x;       // 512 threads, 16 warps
    const int warp = tid >> 5, lane = tid & 31;

    __shared__ float sw[D2];
    __shared__ float sc[TT];
    __shared__ float red[512];
    __shared__ float pooled[D2];

    if (tid < D2) sw[tid] = attn_w[tid];
    __syncthreads();

    const float* __restrict__ zb = &g_z1[(size_t)b * TT][0];
    const float ab = attn_b[0];

    // scores: warp per t, 16 warps -> 64 t each
    for (int t = warp; t < TT; t += 16) {
        const float* zt = zb + (size_t)t * D2;
        float s = 0.f;
        #pragma unroll
        for (int d = lane; d < D2; d += 32) s += zt[d] * sw[d];
        #pragma unroll
        for (int o = 16; o; o >>= 1) s += __shfl_xor_sync(0xffffffffu, s, o);
        if (lane == 0) sc[t] = s + ab;
    }
    __syncthreads();

    // softmax over T (512-wide reduce)
    float m = -INFINITY;
    for (int t = tid; t < TT; t += 512) m = fmaxf(m, sc[t]);
    red[tid] = m; __syncthreads();
    for (int s = 256; s; s >>= 1) {
        if (tid < s) red[tid] = fmaxf(red[tid], red[tid + s]);
        __syncthreads();
    }
    m = red[0]; __syncthreads();

    float sum = 0.f;
    for (int t = tid; t < TT; t += 512) {
        float e = __expf(sc[t] - m);
        sc[t] = e;
        sum += e;
    }
    red[tid] = sum; __syncthreads();
    for (int s = 256; s; s >>= 1) {
        if (tid < s) red[tid] += red[tid + s];
        __syncthreads();
    }
    const float inv = 1.f / red[0];
    __syncthreads();

    // pooled: two t-halves in parallel (d = tid&255, half = tid>>8)
    {
        const int d = tid & 255;
        const int half = tid >> 8;
        float acc = 0.f;
        const int tb = half * (TT / 2);
        #pragma unroll 8
        for (int t = 0; t < TT / 2; ++t)
            acc += sc[tb + t] * zb[(size_t)(tb + t) * D2 + d];
        red[tid] = acc;
    }
    __syncthreads();
    if (tid < D2) pooled[tid] = (red[tid] + red[tid + 256]) * inv;
    __syncthreads();

    // heads: 5 motor + 2 state logits, one warp each
    if (warp < 7) {
        const float* wv;
        float bv;
        int mk = motor_k[b];
        if (warp < 5) { wv = motor_w + warp * D2;              bv = motor_b[warp]; }
        else          { int c = warp - 5;
                        wv = state_w + (size_t)(mk * 2 + c) * D2;
                        bv = state_b[mk * 2 + c]; }
        float s = 0.f;
        #pragma unroll
        for (int d = lane; d < D2; d += 32) s += pooled[d] * wv[d];
        #pragma unroll
        for (int o = 16; o; o >>= 1) s += __shfl_xor_sync(0xffffffffu, s, o);
        if (lane == 0) {
            if (warp < 5) out[b * 5 + warp] = s + bv;
            else          out[BATCH * 5 + b * 2 + (warp - 5)] = s + bv;
        }
    }
}

// ---------------- launch ----------------------------------------------------
extern "C" void kernel_launch(void* const* d_in, const int* in_sizes, int n_in,
                              void* d_out, int out_size)
{
    const float* x        = (const float*)d_in[0];
    const int*   motor_k  = (const int*)  d_in[1];
    const float* wih_l0f  = (const float*)d_in[2];
    const float* whh_l0f  = (const float*)d_in[3];
    const float* bih_l0f  = (const float*)d_in[4];
    const float* bhh_l0f  = (const float*)d_in[5];
    const float* wih_l0b  = (const float*)d_in[6];
    const float* whh_l0b  = (const float*)d_in[7];
    const float* bih_l0b  = (const float*)d_in[8];
    const float* bhh_l0b  = (const float*)d_in[9];
    const float* wih_l1f  = (const float*)d_in[10];
    const float* whh_l1f  = (const float*)d_in[11];
    const float* bih_l1f  = (const float*)d_in[12];
    const float* bhh_l1f  = (const float*)d_in[13];
    const float* wih_l1b  = (const float*)d_in[14];
    const float* whh_l1b  = (const float*)d_in[15];
    const float* bih_l1b  = (const float*)d_in[16];
    const float* bhh_l1b  = (const float*)d_in[17];
    const float* attn_w   = (const float*)d_in[18];
    const float* attn_b   = (const float*)d_in[19];
    const float* motor_w  = (const float*)d_in[20];
    const float* motor_b  = (const float*)d_in[21];
    const float* state_w  = (const float*)d_in[22];
    const float* state_b  = (const float*)d_in[23];
    float* out = (float*)d_out;

    // single fused bf16 (hi,lo) conversion pass
    convert_all_kernel<<<2368, 256>>>(x, wih_l0f, wih_l0b, wih_l1f, wih_l1b);

    dim3 gproj(MROWS / 128, G3 / 128, 2);   // 512 x 3 x 2

    // layer 0
    mma_proj_kernel<<<gproj, 256>>>(bih_l0f, bih_l0b, bhh_l0f, bhh_l0b, DIN, 0);
    gru_scan_kernel<<<BATCH * 2, 384>>>(whh_l0f, whh_l0b, bhh_l0f, bhh_l0b, 0);
    // layer 1
    mma_proj_kernel<<<gproj, 256>>>(bih_l1f, bih_l1b, bhh_l1f, bhh_l1b, D2, 1);
    gru_scan_kernel<<<BATCH * 2, 384>>>(whh_l1f, whh_l1b, bhh_l1f, bhh_l1b, 1);
    // pooling + heads
    attn_head_kernel<<<BATCH, 512>>>(attn_w, attn_b, motor_w, motor_b,
                                     state_w, state_b, motor_k, out);
}

// round 12
// speedup vs baseline: 1.0052x; 1.0052x over previous
#include <cuda_runtime.h>
#include <cuda_bf16.h>
#include <math.h>
#include <stdint.h>

// Problem constants
#define BATCH 64
#define TT    1024
#define DIN   64
#define HID   128
#define G3    384   // 3*HID
#define D2    256   // 2*HID
#define MROWS (BATCH*TT)   // 65536

typedef unsigned long long ull;

// ---------------- f32x2 packed helpers (sm_103a FFMA2) ----------------------
__device__ __forceinline__ ull fma2(ull a, ull b, ull c) {
    ull d;
    asm("fma.rn.f32x2 %0, %1, %2, %3;" : "=l"(d) : "l"(a), "l"(b), "l"(c));
    return d;
}
__device__ __forceinline__ float2 unpack2(ull v) {
    float2 r;
    asm("mov.b64 {%0, %1}, %2;" : "=f"(r.x), "=f"(r.y) : "l"(v));
    return r;
}
__device__ __forceinline__ float sigm(float x) {
    return 1.f / (1.f + __expf(-x));
}
__device__ __forceinline__ float ftanh(float x) {
    return __fmaf_rn(2.f, 1.f / (1.f + __expf(-2.f * x)), -1.f);
}

// ---------------- bf16 HMMA (m16n8k16) --------------------------------------
__device__ __forceinline__ void mma_bf16(float* c,
                                         uint32_t a0, uint32_t a1, uint32_t a2, uint32_t a3,
                                         uint32_t b0, uint32_t b1) {
    asm volatile(
        "mma.sync.aligned.m16n8k16.row.col.f32.bf16.bf16.f32 "
        "{%0,%1,%2,%3}, {%4,%5,%6,%7}, {%8,%9}, {%0,%1,%2,%3};"
        : "+f"(c[0]), "+f"(c[1]), "+f"(c[2]), "+f"(c[3])
        : "r"(a0), "r"(a1), "r"(a2), "r"(a3), "r"(b0), "r"(b1));
}

// ---------------- scratch (device globals; no allocation allowed) ----------
__device__ float g_xW[2][MROWS][G3];          // input projections per dir
__device__ float g_z1[MROWS][D2];             // layer-1 output (fp32 for attn)
__device__ __nv_bfloat16 g_xh[MROWS * DIN],  g_xl[MROWS * DIN];
__device__ __nv_bfloat16 g_z0h[MROWS * D2],  g_z0l[MROWS * D2];
__device__ __nv_bfloat16 g_w0h[2][G3 * DIN], g_w0l[2][G3 * DIN];
__device__ __nv_bfloat16 g_w1h[2][G3 * D2],  g_w1l[2][G3 * D2];

// ---------------- fused fp32 -> bf16 (hi, lo) split conversion -------------
#define XN  (MROWS * DIN)
#define W0N (G3 * DIN)
#define W1N (G3 * D2)
__global__ __launch_bounds__(256)
void convert_all_kernel(const float* __restrict__ x,
                        const float* __restrict__ w0f, const float* __restrict__ w0b,
                        const float* __restrict__ w1f, const float* __restrict__ w1b)
{
    const int total = XN + 2 * W0N + 2 * W1N;
    for (int i = blockIdx.x * 256 + threadIdx.x; i < total; i += gridDim.x * 256) {
        const float* src;
        __nv_bfloat16 *hi, *lo;
        int k = i;
        if (k < XN)                    { src = x;   hi = g_xh;     lo = g_xl;     }
        else if ((k -= XN) < W0N)      { src = w0f; hi = g_w0h[0]; lo = g_w0l[0]; }
        else if ((k -= W0N) < W0N)     { src = w0b; hi = g_w0h[1]; lo = g_w0l[1]; }
        else if ((k -= W0N) < W1N)     { src = w1f; hi = g_w1h[0]; lo = g_w1l[0]; }
        else      { k -= W1N;            src = w1b; hi = g_w1h[1]; lo = g_w1l[1]; }
        float v = src[k];
        __nv_bfloat16 h = __float2bfloat16(v);
        hi[k] = h;
        lo[k] = __float2bfloat16(v - __bfloat162float(h));
    }
}

// ---------------- HMMA projection GEMM — double-buffered smem --------------
// BM=128, BN=128, BK=32; 256 thr; 3-plane bf16 split; one barrier per chunk.
#define LDP 40
#define PLANE (128 * LDP)        // elements per plane
#define BUFE  (4 * PLANE)        // elements per buffer (4 planes)
#define SMEM_PROJ_BYTES (2 * BUFE * 2)   // 2 buffers * bf16

__global__ __launch_bounds__(256, 1)
void mma_proj_kernel(const float* __restrict__ bf,  const float* __restrict__ bb,
                     const float* __restrict__ bhf, const float* __restrict__ bhb,
                     int K, int layer)
{
    extern __shared__ __nv_bfloat16 dynbf[];
    __shared__ float sBias[128];

    const int tid  = threadIdx.x;
    const int wid  = tid >> 5;
    const int lane = tid & 31;
    const int g    = lane >> 2;
    const int tig  = lane & 3;
    const int wr   = wid >> 1;
    const int wc   = wid & 1;
    const int m0   = blockIdx.x * 128;
    const int n0   = blockIdx.y * 128;
    const int dir  = blockIdx.z;

    const __nv_bfloat16* __restrict__ Ah = layer ? g_z0h : g_xh;
    const __nv_bfloat16* __restrict__ Al = layer ? g_z0l : g_xl;
    const __nv_bfloat16* __restrict__ Wh = layer ? g_w1h[dir] : g_w0h[dir];
    const __nv_bfloat16* __restrict__ Wl = layer ? g_w1l[dir] : g_w0l[dir];
    const float* __restrict__ bias = dir ? bb : bf;
    const float* __restrict__ bhh  = dir ? bhb : bhf;

    if (tid < 128) {
        int c = n0 + tid;
        sBias[tid] = bias[c] + (c < 2 * HID ? bhh[c] : 0.f);
    }

    const int lr0 = tid >> 1;
    const int lc0 = (tid & 1) * 16;

    float acc[2][8][4];
    #pragma unroll
    for (int a = 0; a < 2; ++a)
        #pragma unroll
        for (int b = 0; b < 8; ++b)
            #pragma unroll
            for (int cc = 0; cc < 4; ++cc) acc[a][b][cc] = 0.f;

    const int nchunks = K >> 5;

    // stage chunk 0 into buffer 0
    {
        const size_t ga = (size_t)(m0 + lr0) * K + lc0;
        const size_t gw = (size_t)(n0 + lr0) * K + lc0;
        __nv_bfloat16* b0 = dynbf;
        *(uint4*)&b0[0*PLANE + lr0*LDP + lc0]     = *(const uint4*)(Ah + ga);
        *(uint4*)&b0[0*PLANE + lr0*LDP + lc0 + 8] = *(const uint4*)(Ah + ga + 8);
        *(uint4*)&b0[1*PLANE + lr0*LDP + lc0]     = *(const uint4*)(Al + ga);
        *(uint4*)&b0[1*PLANE + lr0*LDP + lc0 + 8] = *(const uint4*)(Al + ga + 8);
        *(uint4*)&b0[2*PLANE + lr0*LDP + lc0]     = *(const uint4*)(Wh + gw);
        *(uint4*)&b0[2*PLANE + lr0*LDP + lc0 + 8] = *(const uint4*)(Wh + gw + 8);
        *(uint4*)&b0[3*PLANE + lr0*LDP + lc0]     = *(const uint4*)(Wl + gw);
        *(uint4*)&b0[3*PLANE + lr0*LDP + lc0 + 8] = *(const uint4*)(Wl + gw + 8);
    }
    __syncthreads();

    for (int c = 0; c < nchunks; ++c) {
        const __nv_bfloat16* cur = dynbf + (c & 1) * BUFE;
        const __nv_bfloat16* sAh = cur;
        const __nv_bfloat16* sAl = cur + PLANE;
        const __nv_bfloat16* sWh = cur + 2 * PLANE;
        const __nv_bfloat16* sWl = cur + 3 * PLANE;

        // prefetch chunk c+1 to registers, store into the OTHER buffer
        // (safe: end-of-(c-1) barrier guaranteed all reads of that buffer done)
        if (c + 1 < nchunks) {
            const size_t ga = (size_t)(m0 + lr0) * K + (c + 1) * 32 + lc0;
            const size_t gw = (size_t)(n0 + lr0) * K + (c + 1) * 32 + lc0;
            uint4 a0 = *(const uint4*)(Ah + ga), a1 = *(const uint4*)(Ah + ga + 8);
            uint4 l0 = *(const uint4*)(Al + ga), l1 = *(const uint4*)(Al + ga + 8);
            uint4 h0 = *(const uint4*)(Wh + gw), h1 = *(const uint4*)(Wh + gw + 8);
            uint4 q0 = *(const uint4*)(Wl + gw), q1 = *(const uint4*)(Wl + gw + 8);
            __nv_bfloat16* nb = dynbf + ((c + 1) & 1) * BUFE;
            *(uint4*)&nb[0*PLANE + lr0*LDP + lc0]     = a0;
            *(uint4*)&nb[0*PLANE + lr0*LDP + lc0 + 8] = a1;
            *(uint4*)&nb[1*PLANE + lr0*LDP + lc0]     = l0;
            *(uint4*)&nb[1*PLANE + lr0*LDP + lc0 + 8] = l1;
            *(uint4*)&nb[2*PLANE + lr0*LDP + lc0]     = h0;
            *(uint4*)&nb[2*PLANE + lr0*LDP + lc0 + 8] = h1;
            *(uint4*)&nb[3*PLANE + lr0*LDP + lc0]     = q0;
            *(uint4*)&nb[3*PLANE + lr0*LDP + lc0 + 8] = q1;
        }

        #pragma unroll
        for (int ks = 0; ks < 2; ++ks) {
            const int kc = ks * 16 + tig * 2;
            uint32_t ah[2][4], al[2][4];
            #pragma unroll
            for (int mt = 0; mt < 2; ++mt) {
                const int r = wr * 32 + mt * 16 + g;
                ah[mt][0] = *(const uint32_t*)&sAh[r*LDP + kc];
                ah[mt][1] = *(const uint32_t*)&sAh[(r + 8)*LDP + kc];
                ah[mt][2] = *(const uint32_t*)&sAh[r*LDP + kc + 8];
                ah[mt][3] = *(const uint32_t*)&sAh[(r + 8)*LDP + kc + 8];
                al[mt][0] = *(const uint32_t*)&sAl[r*LDP + kc];
                al[mt][1] = *(const uint32_t*)&sAl[(r + 8)*LDP + kc];
                al[mt][2] = *(const uint32_t*)&sAl[r*LDP + kc + 8];
                al[mt][3] = *(const uint32_t*)&sAl[(r + 8)*LDP + kc + 8];
            }
            #pragma unroll
            for (int nt = 0; nt < 8; ++nt) {
                const int wn = wc * 64 + nt * 8 + g;
                uint32_t bh0 = *(const uint32_t*)&sWh[wn*LDP + kc];
                uint32_t bh1 = *(const uint32_t*)&sWh[wn*LDP + kc + 8];
                uint32_t bl0 = *(const uint32_t*)&sWl[wn*LDP + kc];
                uint32_t bl1 = *(const uint32_t*)&sWl[wn*LDP + kc + 8];
                #pragma unroll
                for (int mt = 0; mt < 2; ++mt) {
                    mma_bf16(acc[mt][nt], ah[mt][0], ah[mt][1], ah[mt][2], ah[mt][3], bh0, bh1);
                    mma_bf16(acc[mt][nt], ah[mt][0], ah[mt][1], ah[mt][2], ah[mt][3], bl0, bl1);
                    mma_bf16(acc[mt][nt], al[mt][0], al[mt][1], al[mt][2], al[mt][3], bh0, bh1);
                }
            }
        }
        __syncthreads();   // single barrier: reads of cur done, next buffer visible
    }

    float* Cout = &g_xW[dir][0][0];
    #pragma unroll
    for (int mt = 0; mt < 2; ++mt) {
        const int mrow = m0 + wr * 32 + mt * 16 + g;
        #pragma unroll
        for (int nt = 0; nt < 8; ++nt) {
            const int ncol  = wc * 64 + nt * 8 + tig * 2;
            const int gcol  = n0 + ncol;
            float2 o0 = {acc[mt][nt][0] + sBias[ncol],
                         acc[mt][nt][1] + sBias[ncol + 1]};
            float2 o1 = {acc[mt][nt][2] + sBias[ncol],
                         acc[mt][nt][3] + sBias[ncol + 1]};
            *(float2*)(Cout + (size_t)mrow * G3 + gcol)       = o0;
            *(float2*)(Cout + (size_t)(mrow + 8) * G3 + gcol) = o1;
        }
    }
}

// ---------------- GRU recurrence (R5/R8/R10 structure — converged) ---------
__global__ __launch_bounds__(384, 1)
void gru_scan_kernel(const float* __restrict__ whh_f, const float* __restrict__ whh_b,
                     const float* __restrict__ bhh_f, const float* __restrict__ bhh_b,
                     int layer)
{
    const int b   = blockIdx.x >> 1;
    const int dir = blockIdx.x & 1;
    const int j   = threadIdx.x;                 // 0..383 = gate row

    const float* __restrict__ whh = dir ? whh_b : whh_f;
    const float* __restrict__ bhh = dir ? bhh_b : bhh_f;

    __shared__ __align__(16) float h_s[HID];
    __shared__ float rz_s[2 * HID];

    ull w2[64];
    #pragma unroll
    for (int i = 0; i < 64; i += 2) {
        ulonglong2 v = *(const ulonglong2*)(whh + (size_t)j * HID + 2 * i);
        w2[i] = v.x; w2[i + 1] = v.y;
    }
    const bool is_n = (j >= 2 * HID);
    const int  o    = j - 2 * HID;
    const float bj  = is_n ? bhh[j] : 0.f;       // bhh_n stays inside r*(.)
    float hreg = 0.f;
    if (j < HID) h_s[j] = 0.f;

    const float* __restrict__ gi = &g_xW[dir][(size_t)b * TT][0];
    float* __restrict__ zf = &g_z1[(size_t)b * TT][0] + dir * HID;
    __nv_bfloat16* __restrict__ zh = g_z0h + (size_t)b * TT * D2 + dir * HID;
    __nv_bfloat16* __restrict__ zl = g_z0l + (size_t)b * TT * D2 + dir * HID;

    const int t0 = dir ? (TT - 1) : 0;
    float gi_v = __ldcs(gi + (size_t)t0 * G3 + j);
    __syncthreads();

    for (int t = 0; t < TT; ++t) {
        const int tt = dir ? (TT - 1 - t) : t;

        float pre = 0.f;
        if (t + 1 < TT) {
            const int tn = dir ? (TT - 2 - t) : (t + 1);
            pre = __ldcs(gi + (size_t)tn * G3 + j);
        }

        ull a0 = 0ull, a1 = 0ull;
        const ull* h2 = (const ull*)h_s;
        #pragma unroll
        for (int i = 0; i < 64; i += 8) {
            ulonglong2 hv0 = *(const ulonglong2*)(h2 + i);
            ulonglong2 hv1 = *(const ulonglong2*)(h2 + i + 2);
            ulonglong2 hv2 = *(const ulonglong2*)(h2 + i + 4);
            ulonglong2 hv3 = *(const ulonglong2*)(h2 + i + 6);
            a0 = fma2(w2[i],     hv0.x, a0);
            a1 = fma2(w2[i + 1], hv0.y, a1);
            a0 = fma2(w2[i + 2], hv1.x, a0);
            a1 = fma2(w2[i + 3], hv1.y, a1);
            a0 = fma2(w2[i + 4], hv2.x, a0);
            a1 = fma2(w2[i + 5], hv2.y, a1);
            a0 = fma2(w2[i + 6], hv3.x, a0);
            a1 = fma2(w2[i + 7], hv3.y, a1);
        }
        float2 s0 = unpack2(a0), s1 = unpack2(a1);
        float gh = (s0.x + s0.y) + (s1.x + s1.y);

        if (!is_n) rz_s[j] = sigm(gi_v + gh);
        __syncthreads();

        if (is_n) {
            float r  = rz_s[o];
            float zg = rz_s[HID + o];
            float n  = ftanh(gi_v + r * (gh + bj));
            hreg = (1.f - zg) * n + zg * hreg;
            h_s[o] = hreg;
            if (layer) {
                zf[(size_t)tt * D2 + o] = hreg;
            } else {
                __nv_bfloat16 hi = __float2bfloat16(hreg);
                zh[(size_t)tt * D2 + o] = hi;
                zl[(size_t)tt * D2 + o] = __float2bfloat16(hreg - __bfloat162float(hi));
            }
        }
        gi_v = pre;
        __syncthreads();
    }
}

// ---------------- attention pooling + heads (R10 — proven) -----------------
__global__ __launch_bounds__(256)
void attn_head_kernel(const float* __restrict__ attn_w, const float* __restrict__ attn_b,
                      const float* __restrict__ motor_w, const float* __restrict__ motor_b,
                      const float* __restrict__ state_w, const float* __restrict__ state_b,
                      const int* __restrict__ motor_k, float* __restrict__ out)
{
    const int b = blockIdx.x;
    const int tid = threadIdx.x;       // 256 threads
    const int warp = tid >> 5, lane = tid & 31;

    __shared__ float sw[D2];
    __shared__ float sc[TT];
    __shared__ float red[256];
    __shared__ float pooled[D2];

    sw[tid] = attn_w[tid];
    __syncthreads();

    const float* __restrict__ zb = &g_z1[(size_t)b * TT][0];
    const float ab = attn_b[0];

    for (int t = warp; t < TT; t += 8) {
        const float* zt = zb + (size_t)t * D2;
        float s = 0.f;
        #pragma unroll
        for (int d = lane; d < D2; d += 32) s += zt[d] * sw[d];
        #pragma unroll
        for (int o = 16; o; o >>= 1) s += __shfl_xor_sync(0xffffffffu, s, o);
        if (lane == 0) sc[t] = s + ab;
    }
    __syncthreads();

    float m = -INFINITY;
    for (int t = tid; t < TT; t += 256) m = fmaxf(m, sc[t]);
    red[tid] = m; __syncthreads();
    for (int s = 128; s; s >>= 1) {
        if (tid < s) red[tid] = fmaxf(red[tid], red[tid + s]);
        __syncthreads();
    }
    m = red[0]; __syncthreads();

    float sum = 0.f;
    for (int t = tid; t < TT; t += 256) {
        float e = __expf(sc[t] - m);
        sc[t] = e;
        sum += e;
    }
    red[tid] = sum; __syncthreads();
    for (int s = 128; s; s >>= 1) {
        if (tid < s) red[tid] += red[tid + s];
        __syncthreads();
    }
    const float inv = 1.f / red[0];
    __syncthreads();

    float acc = 0.f;
    #pragma unroll 8
    for (int t = 0; t < TT; ++t) acc += sc[t] * zb[(size_t)t * D2 + tid];
    pooled[tid] = acc * inv;
    __syncthreads();

    if (warp < 7) {
        const float* wv;
        float bv;
        int mk = motor_k[b];
        if (warp < 5) { wv = motor_w + warp * D2;              bv = motor_b[warp]; }
        else          { int c = warp - 5;
                        wv = state_w + (size_t)(mk * 2 + c) * D2;
                        bv = state_b[mk * 2 + c]; }
        float s = 0.f;
        #pragma unroll
        for (int d = lane; d < D2; d += 32) s += pooled[d] * wv[d];
        #pragma unroll
        for (int o = 16; o; o >>= 1) s += __shfl_xor_sync(0xffffffffu, s, o);
        if (lane == 0) {
            if (warp < 5) out[b * 5 + warp] = s + bv;
            else          out[BATCH * 5 + b * 2 + (warp - 5)] = s + bv;
        }
    }
}

// ---------------- launch ----------------------------------------------------
extern "C" void kernel_launch(void* const* d_in, const int* in_sizes, int n_in,
                              void* d_out, int out_size)
{
    const float* x        = (const float*)d_in[0];
    const int*   motor_k  = (const int*)  d_in[1];
    const float* wih_l0f  = (const float*)d_in[2];
    const float* whh_l0f  = (const float*)d_in[3];
    const float* bih_l0f  = (const float*)d_in[4];
    const float* bhh_l0f  = (const float*)d_in[5];
    const float* wih_l0b  = (const float*)d_in[6];
    const float* whh_l0b  = (const float*)d_in[7];
    const float* bih_l0b  = (const float*)d_in[8];
    const float* bhh_l0b  = (const float*)d_in[9];
    const float* wih_l1f  = (const float*)d_in[10];
    const float* whh_l1f  = (const float*)d_in[11];
    const float* bih_l1f  = (const float*)d_in[12];
    const float* bhh_l1f  = (const float*)d_in[13];
    const float* wih_l1b  = (const float*)d_in[14];
    const float* whh_l1b  = (const float*)d_in[15];
    const float* bih_l1b  = (const float*)d_in[16];
    const float* bhh_l1b  = (const float*)d_in[17];
    const float* attn_w   = (const float*)d_in[18];
    const float* attn_b   = (const float*)d_in[19];
    const float* motor_w  = (const float*)d_in[20];
    const float* motor_b  = (const float*)d_in[21];
    const float* state_w  = (const float*)d_in[22];
    const float* state_b  = (const float*)d_in[23];
    float* out = (float*)d_out;

    cudaFuncSetAttribute(mma_proj_kernel,
                         cudaFuncAttributeMaxDynamicSharedMemorySize, SMEM_PROJ_BYTES);

    // single fused bf16 (hi,lo) conversion pass
    convert_all_kernel<<<2368, 256>>>(x, wih_l0f, wih_l0b, wih_l1f, wih_l1b);

    dim3 gproj(MROWS / 128, G3 / 128, 2);   // 512 x 3 x 2

    // layer 0
    mma_proj_kernel<<<gproj, 256, SMEM_PROJ_BYTES>>>(bih_l0f, bih_l0b,
                                                     bhh_l0f, bhh_l0b, DIN, 0);
    gru_scan_kernel<<<BATCH * 2, 384>>>(whh_l0f, whh_l0b, bhh_l0f, bhh_l0b, 0);
    // layer 1
    mma_proj_kernel<<<gproj, 256, SMEM_PROJ_BYTES>>>(bih_l1f, bih_l1b,
                                                     bhh_l1f, bhh_l1b, D2, 1);
    gru_scan_kernel<<<BATCH * 2, 384>>>(whh_l1f, whh_l1b, bhh_l1f, bhh_l1b, 1);
    // pooling + heads
    attn_head_kernel<<<BATCH, 256>>>(attn_w, attn_b, motor_w, motor_b,
                                     state_w, state_b, motor_k, out);
}

// round 13
// speedup vs baseline: 1.0391x; 1.0337x over previous
#include <cuda_runtime.h>
#include <cuda_bf16.h>
#include <math.h>
#include <stdint.h>

// Problem constants
#define BATCH 64
#define TT    1024
#define DIN   64
#define HID   128
#define G3    384   // 3*HID
#define D2    256   // 2*HID
#define MROWS (BATCH*TT)   // 65536

typedef unsigned long long ull;

// ---------------- f32x2 packed helpers (sm_103a FFMA2) ----------------------
__device__ __forceinline__ ull fma2(ull a, ull b, ull c) {
    ull d;
    asm("fma.rn.f32x2 %0, %1, %2, %3;" : "=l"(d) : "l"(a), "l"(b), "l"(c));
    return d;
}
__device__ __forceinline__ float2 unpack2(ull v) {
    float2 r;
    asm("mov.b64 {%0, %1}, %2;" : "=f"(r.x), "=f"(r.y) : "l"(v));
    return r;
}
__device__ __forceinline__ float sigm(float x) {
    return 1.f / (1.f + __expf(-x));
}
__device__ __forceinline__ float ftanh(float x) {
    return __fmaf_rn(2.f, 1.f / (1.f + __expf(-2.f * x)), -1.f);
}

// ---------------- bf16 HMMA (m16n8k16) --------------------------------------
__device__ __forceinline__ void mma_bf16(float* c,
                                         uint32_t a0, uint32_t a1, uint32_t a2, uint32_t a3,
                                         uint32_t b0, uint32_t b1) {
    asm volatile(
        "mma.sync.aligned.m16n8k16.row.col.f32.bf16.bf16.f32 "
        "{%0,%1,%2,%3}, {%4,%5,%6,%7}, {%8,%9}, {%0,%1,%2,%3};"
        : "+f"(c[0]), "+f"(c[1]), "+f"(c[2]), "+f"(c[3])
        : "r"(a0), "r"(a1), "r"(a2), "r"(a3), "r"(b0), "r"(b1));
}

// ---------------- scratch (device globals; no allocation allowed) ----------
__device__ float g_xW[2][MROWS][G3];          // input projections per dir
__device__ float g_z1[MROWS][D2];             // layer-1 output (fp32 for attn)
__device__ __nv_bfloat16 g_xh[MROWS * DIN],  g_xl[MROWS * DIN];
__device__ __nv_bfloat16 g_z0h[MROWS * D2],  g_z0l[MROWS * D2];
__device__ __nv_bfloat16 g_w0h[2][G3 * DIN], g_w0l[2][G3 * DIN];
__device__ __nv_bfloat16 g_w1h[2][G3 * D2],  g_w1l[2][G3 * D2];

// ---------------- fused fp32 -> bf16 (hi, lo) split conversion -------------
#define XN  (MROWS * DIN)
#define W0N (G3 * DIN)
#define W1N (G3 * D2)
__global__ __launch_bounds__(256)
void convert_all_kernel(const float* __restrict__ x,
                        const float* __restrict__ w0f, const float* __restrict__ w0b,
                        const float* __restrict__ w1f, const float* __restrict__ w1b)
{
    const int total = XN + 2 * W0N + 2 * W1N;
    for (int i = blockIdx.x * 256 + threadIdx.x; i < total; i += gridDim.x * 256) {
        const float* src;
        __nv_bfloat16 *hi, *lo;
        int k = i;
        if (k < XN)                    { src = x;   hi = g_xh;     lo = g_xl;     }
        else if ((k -= XN) < W0N)      { src = w0f; hi = g_w0h[0]; lo = g_w0l[0]; }
        else if ((k -= W0N) < W0N)     { src = w0b; hi = g_w0h[1]; lo = g_w0l[1]; }
        else if ((k -= W0N) < W1N)     { src = w1f; hi = g_w1h[0]; lo = g_w1l[0]; }
        else      { k -= W1N;            src = w1b; hi = g_w1h[1]; lo = g_w1l[1]; }
        float v = src[k];
        __nv_bfloat16 h = __float2bfloat16(v);
        hi[k] = h;
        lo[k] = __float2bfloat16(v - __bfloat162float(h));
    }
}

// ---------------- HMMA projection GEMM (R10 structure, BN=64, 2 CTAs/SM) ---
// BM=128, BN=64, BK=32; 256 thr = 8 warps (4 m x 2 n), warp = 32m x 32n.
// Same LDG->compute->STS ordering as the proven R10 kernel; smaller tile
// halves regs/smem so 2 CTAs co-reside per SM (16 warps of latency cover).
#define LDP 40
__global__ __launch_bounds__(256, 2)
void mma_proj_kernel(const float* __restrict__ bf,  const float* __restrict__ bb,
                     const float* __restrict__ bhf, const float* __restrict__ bhb,
                     int K, int layer)
{
    __shared__ __align__(16) __nv_bfloat16 sAh[128][LDP];
    __shared__ __align__(16) __nv_bfloat16 sAl[128][LDP];
    __shared__ __align__(16) __nv_bfloat16 sWh[64][LDP];
    __shared__ __align__(16) __nv_bfloat16 sWl[64][LDP];
    __shared__ float sBias[64];

    const int tid  = threadIdx.x;
    const int wid  = tid >> 5;
    const int lane = tid & 31;
    const int g    = lane >> 2;
    const int tig  = lane & 3;
    const int wr   = wid >> 1;           // 0..3  m offset wr*32
    const int wc   = wid & 1;            // 0..1  n offset wc*32
    const int m0   = blockIdx.x * 128;
    const int n0   = blockIdx.y * 64;
    const int dir  = blockIdx.z;

    const __nv_bfloat16* __restrict__ Ah = layer ? g_z0h : g_xh;
    const __nv_bfloat16* __restrict__ Al = layer ? g_z0l : g_xl;
    const __nv_bfloat16* __restrict__ Wh = layer ? g_w1h[dir] : g_w0h[dir];
    const __nv_bfloat16* __restrict__ Wl = layer ? g_w1l[dir] : g_w0l[dir];
    const float* __restrict__ bias = dir ? bb : bf;
    const float* __restrict__ bhh  = dir ? bhb : bhf;

    if (tid < 64) {
        int c = n0 + tid;
        sBias[tid] = bias[c] + (c < 2 * HID ? bhh[c] : 0.f);
    }

    // A loads: row = tid>>1 (0..127), 2 uint4 at col (tid&1)*16
    const int alr = tid >> 1;
    const int alc = (tid & 1) * 16;
    // W loads: row = tid>>2 (0..63), 1 uint4 at col (tid&3)*8
    const int wlr = tid >> 2;
    const int wlc = (tid & 3) * 8;

    float acc[2][4][4];
    #pragma unroll
    for (int a = 0; a < 2; ++a)
        #pragma unroll
        for (int b = 0; b < 4; ++b)
            #pragma unroll
            for (int cc = 0; cc < 4; ++cc) acc[a][b][cc] = 0.f;

    const int nchunks = K >> 5;

    // prologue: chunk 0 to registers
    uint4 pAh0, pAh1, pAl0, pAl1, pWh0, pWl0;
    {
        const size_t ga = (size_t)(m0 + alr) * K + alc;
        const size_t gw = (size_t)(n0 + wlr) * K + wlc;
        pAh0 = *(const uint4*)(Ah + ga);  pAh1 = *(const uint4*)(Ah + ga + 8);
        pAl0 = *(const uint4*)(Al + ga);  pAl1 = *(const uint4*)(Al + ga + 8);
        pWh0 = *(const uint4*)(Wh + gw);
        pWl0 = *(const uint4*)(Wl + gw);
    }

    for (int c = 0; c < nchunks; ++c) {
        // stage current chunk into smem
        *(uint4*)&sAh[alr][alc] = pAh0;  *(uint4*)&sAh[alr][alc + 8] = pAh1;
        *(uint4*)&sAl[alr][alc] = pAl0;  *(uint4*)&sAl[alr][alc + 8] = pAl1;
        *(uint4*)&sWh[wlr][wlc] = pWh0;
        *(uint4*)&sWl[wlr][wlc] = pWl0;
        __syncthreads();

        // prefetch next chunk to registers (latency hidden under MMA block)
        if (c + 1 < nchunks) {
            const size_t ga = (size_t)(m0 + alr) * K + (c + 1) * 32 + alc;
            const size_t gw = (size_t)(n0 + wlr) * K + (c + 1) * 32 + wlc;
            pAh0 = *(const uint4*)(Ah + ga);  pAh1 = *(const uint4*)(Ah + ga + 8);
            pAl0 = *(const uint4*)(Al + ga);  pAl1 = *(const uint4*)(Al + ga + 8);
            pWh0 = *(const uint4*)(Wh + gw);
            pWl0 = *(const uint4*)(Wl + gw);
        }

        #pragma unroll
        for (int ks = 0; ks < 2; ++ks) {
            const int kc = ks * 16 + tig * 2;
            uint32_t ah[2][4], al[2][4];
            #pragma unroll
            for (int mt = 0; mt < 2; ++mt) {
                const int r = wr * 32 + mt * 16 + g;
                ah[mt][0] = *(const uint32_t*)&sAh[r][kc];
                ah[mt][1] = *(const uint32_t*)&sAh[r + 8][kc];
                ah[mt][2] = *(const uint32_t*)&sAh[r][kc + 8];
                ah[mt][3] = *(const uint32_t*)&sAh[r + 8][kc + 8];
                al[mt][0] = *(const uint32_t*)&sAl[r][kc];
                al[mt][1] = *(const uint32_t*)&sAl[r + 8][kc];
                al[mt][2] = *(const uint32_t*)&sAl[r][kc + 8];
                al[mt][3] = *(const uint32_t*)&sAl[r + 8][kc + 8];
            }
            #pragma unroll
            for (int nt = 0; nt < 4; ++nt) {
                const int wn = wc * 32 + nt * 8 + g;
                uint32_t bh0 = *(const uint32_t*)&sWh[wn][kc];
                uint32_t bh1 = *(const uint32_t*)&sWh[wn][kc + 8];
                uint32_t bl0 = *(const uint32_t*)&sWl[wn][kc];
                uint32_t bl1 = *(const uint32_t*)&sWl[wn][kc + 8];
                #pragma unroll
                for (int mt = 0; mt < 2; ++mt) {
                    mma_bf16(acc[mt][nt], ah[mt][0], ah[mt][1], ah[mt][2], ah[mt][3], bh0, bh1);
                    mma_bf16(acc[mt][nt], ah[mt][0], ah[mt][1], ah[mt][2], ah[mt][3], bl0, bl1);
                    mma_bf16(acc[mt][nt], al[mt][0], al[mt][1], al[mt][2], al[mt][3], bh0, bh1);
                }
            }
        }
        __syncthreads();
    }

    // epilogue
    float* Cout = &g_xW[dir][0][0];
    #pragma unroll
    for (int mt = 0; mt < 2; ++mt) {
        const int mrow = m0 + wr * 32 + mt * 16 + g;
        #pragma unroll
        for (int nt = 0; nt < 4; ++nt) {
            const int ncol = wc * 32 + nt * 8 + tig * 2;
            const int gcol = n0 + ncol;
            float2 o0 = {acc[mt][nt][0] + sBias[ncol],
                         acc[mt][nt][1] + sBias[ncol + 1]};
            float2 o1 = {acc[mt][nt][2] + sBias[ncol],
                         acc[mt][nt][3] + sBias[ncol + 1]};
            *(float2*)(Cout + (size_t)mrow * G3 + gcol)       = o0;
            *(float2*)(Cout + (size_t)(mrow + 8) * G3 + gcol) = o1;
        }
    }
}

// ---------------- GRU recurrence (R5/R8/R10 structure — converged) ---------
__global__ __launch_bounds__(384, 1)
void gru_scan_kernel(const float* __restrict__ whh_f, const float* __restrict__ whh_b,
                     const float* __restrict__ bhh_f, const float* __restrict__ bhh_b,
                     int layer)
{
    const int b   = blockIdx.x >> 1;
    const int dir = blockIdx.x & 1;
    const int j   = threadIdx.x;                 // 0..383 = gate row

    const float* __restrict__ whh = dir ? whh_b : whh_f;
    const float* __restrict__ bhh = dir ? bhh_b : bhh_f;

    __shared__ __align__(16) float h_s[HID];
    __shared__ float rz_s[2 * HID];

    ull w2[64];
    #pragma unroll
    for (int i = 0; i < 64; i += 2) {
        ulonglong2 v = *(const ulonglong2*)(whh + (size_t)j * HID + 2 * i);
        w2[i] = v.x; w2[i + 1] = v.y;
    }
    const bool is_n = (j >= 2 * HID);
    const int  o    = j - 2 * HID;
    const float bj  = is_n ? bhh[j] : 0.f;       // bhh_n stays inside r*(.)
    float hreg = 0.f;
    if (j < HID) h_s[j] = 0.f;

    const float* __restrict__ gi = &g_xW[dir][(size_t)b * TT][0];
    float* __restrict__ zf = &g_z1[(size_t)b * TT][0] + dir * HID;
    __nv_bfloat16* __restrict__ zh = g_z0h + (size_t)b * TT * D2 + dir * HID;
    __nv_bfloat16* __restrict__ zl = g_z0l + (size_t)b * TT * D2 + dir * HID;

    const int t0 = dir ? (TT - 1) : 0;
    float gi_v = __ldcs(gi + (size_t)t0 * G3 + j);
    __syncthreads();

    for (int t = 0; t < TT; ++t) {
        const int tt = dir ? (TT - 1 - t) : t;

        float pre = 0.f;
        if (t + 1 < TT) {
            const int tn = dir ? (TT - 2 - t) : (t + 1);
            pre = __ldcs(gi + (size_t)tn * G3 + j);
        }

        ull a0 = 0ull, a1 = 0ull;
        const ull* h2 = (const ull*)h_s;
        #pragma unroll
        for (int i = 0; i < 64; i += 8) {
            ulonglong2 hv0 = *(const ulonglong2*)(h2 + i);
            ulonglong2 hv1 = *(const ulonglong2*)(h2 + i + 2);
            ulonglong2 hv2 = *(const ulonglong2*)(h2 + i + 4);
            ulonglong2 hv3 = *(const ulonglong2*)(h2 + i + 6);
            a0 = fma2(w2[i],     hv0.x, a0);
            a1 = fma2(w2[i + 1], hv0.y, a1);
            a0 = fma2(w2[i + 2], hv1.x, a0);
            a1 = fma2(w2[i + 3], hv1.y, a1);
            a0 = fma2(w2[i + 4], hv2.x, a0);
            a1 = fma2(w2[i + 5], hv2.y, a1);
            a0 = fma2(w2[i + 6], hv3.x, a0);
            a1 = fma2(w2[i + 7], hv3.y, a1);
        }
        float2 s0 = unpack2(a0), s1 = unpack2(a1);
        float gh = (s0.x + s0.y) + (s1.x + s1.y);

        if (!is_n) rz_s[j] = sigm(gi_v + gh);
        __syncthreads();

        if (is_n) {
            float r  = rz_s[o];
            float zg = rz_s[HID + o];
            float n  = ftanh(gi_v + r * (gh + bj));
            hreg = (1.f - zg) * n + zg * hreg;
            h_s[o] = hreg;
            if (layer) {
                zf[(size_t)tt * D2 + o] = hreg;
            } else {
                __nv_bfloat16 hi = __float2bfloat16(hreg);
                zh[(size_t)tt * D2 + o] = hi;
                zl[(size_t)tt * D2 + o] = __float2bfloat16(hreg - __bfloat162float(hi));
            }
        }
        gi_v = pre;
        __syncthreads();
    }
}

// ---------------- attention pooling + heads (R10 — proven) -----------------
__global__ __launch_bounds__(256)
void attn_head_kernel(const float* __restrict__ attn_w, const float* __restrict__ attn_b,
                      const float* __restrict__ motor_w, const float* __restrict__ motor_b,
                      const float* __restrict__ state_w, const float* __restrict__ state_b,
                      const int* __restrict__ motor_k, float* __restrict__ out)
{
    const int b = blockIdx.x;
    const int tid = threadIdx.x;       // 256 threads
    const int warp = tid >> 5, lane = tid & 31;

    __shared__ float sw[D2];
    __shared__ float sc[TT];
    __shared__ float red[256];
    __shared__ float pooled[D2];

    sw[tid] = attn_w[tid];
    __syncthreads();

    const float* __restrict__ zb = &g_z1[(size_t)b * TT][0];
    const float ab = attn_b[0];

    for (int t = warp; t < TT; t += 8) {
        const float* zt = zb + (size_t)t * D2;
        float s = 0.f;
        #pragma unroll
        for (int d = lane; d < D2; d += 32) s += zt[d] * sw[d];
        #pragma unroll
        for (int o = 16; o; o >>= 1) s += __shfl_xor_sync(0xffffffffu, s, o);
        if (lane == 0) sc[t] = s + ab;
    }
    __syncthreads();

    float m = -INFINITY;
    for (int t = tid; t < TT; t += 256) m = fmaxf(m, sc[t]);
    red[tid] = m; __syncthreads();
    for (int s = 128; s; s >>= 1) {
        if (tid < s) red[tid] = fmaxf(red[tid], red[tid + s]);
        __syncthreads();
    }
    m = red[0]; __syncthreads();

    float sum = 0.f;
    for (int t = tid; t < TT; t += 256) {
        float e = __expf(sc[t] - m);
        sc[t] = e;
        sum += e;
    }
    red[tid] = sum; __syncthreads();
    for (int s = 128; s; s >>= 1) {
        if (tid < s) red[tid] += red[tid + s];
        __syncthreads();
    }
    const float inv = 1.f / red[0];
    __syncthreads();

    float acc = 0.f;
    #pragma unroll 8
    for (int t = 0; t < TT; ++t) acc += sc[t] * zb[(size_t)t * D2 + tid];
    pooled[tid] = acc * inv;
    __syncthreads();

    if (warp < 7) {
        const float* wv;
        float bv;
        int mk = motor_k[b];
        if (warp < 5) { wv = motor_w + warp * D2;              bv = motor_b[warp]; }
        else          { int c = warp - 5;
                        wv = state_w + (size_t)(mk * 2 + c) * D2;
                        bv = state_b[mk * 2 + c]; }
        float s = 0.f;
        #pragma unroll
        for (int d = lane; d < D2; d += 32) s += pooled[d] * wv[d];
        #pragma unroll
        for (int o = 16; o; o >>= 1) s += __shfl_xor_sync(0xffffffffu, s, o);
        if (lane == 0) {
            if (warp < 5) out[b * 5 + warp] = s + bv;
            else          out[BATCH * 5 + b * 2 + (warp - 5)] = s + bv;
        }
    }
}

// ---------------- launch ----------------------------------------------------
extern "C" void kernel_launch(void* const* d_in, const int* in_sizes, int n_in,
                              void* d_out, int out_size)
{
    const float* x        = (const float*)d_in[0];
    const int*   motor_k  = (const int*)  d_in[1];
    const float* wih_l0f  = (const float*)d_in[2];
    const float* whh_l0f  = (const float*)d_in[3];
    const float* bih_l0f  = (const float*)d_in[4];
    const float* bhh_l0f  = (const float*)d_in[5];
    const float* wih_l0b  = (const float*)d_in[6];
    const float* whh_l0b  = (const float*)d_in[7];
    const float* bih_l0b  = (const float*)d_in[8];
    const float* bhh_l0b  = (const float*)d_in[9];
    const float* wih_l1f  = (const float*)d_in[10];
    const float* whh_l1f  = (const float*)d_in[11];
    const float* bih_l1f  = (const float*)d_in[12];
    const float* bhh_l1f  = (const float*)d_in[13];
    const float* wih_l1b  = (const float*)d_in[14];
    const float* whh_l1b  = (const float*)d_in[15];
    const float* bih_l1b  = (const float*)d_in[16];
    const float* bhh_l1b  = (const float*)d_in[17];
    const float* attn_w   = (const float*)d_in[18];
    const float* attn_b   = (const float*)d_in[19];
    const float* motor_w  = (const float*)d_in[20];
    const float* motor_b  = (const float*)d_in[21];
    const float* state_w  = (const float*)d_in[22];
    const float* state_b  = (const float*)d_in[23];
    float* out = (float*)d_out;

    // single fused bf16 (hi,lo) conversion pass
    convert_all_kernel<<<2368, 256>>>(x, wih_l0f, wih_l0b, wih_l1f, wih_l1b);

    dim3 gproj(MROWS / 128, G3 / 64, 2);   // 512 x 6 x 2

    // layer 0
    mma_proj_kernel<<<gproj, 256>>>(bih_l0f, bih_l0b, bhh_l0f, bhh_l0b, DIN, 0);
    gru_scan_kernel<<<BATCH * 2, 384>>>(whh_l0f, whh_l0b, bhh_l0f, bhh_l0b, 0);
    // layer 1
    mma_proj_kernel<<<gproj, 256>>>(bih_l1f, bih_l1b, bhh_l1f, bhh_l1b, D2, 1);
    gru_scan_kernel<<<BATCH * 2, 384>>>(whh_l1f, whh_l1b, bhh_l1f, bhh_l1b, 1);
    // pooling + heads
    attn_head_kernel<<<BATCH, 256>>>(attn_w, attn_b, motor_w, motor_b,
                                     state_w, state_b, motor_k, out);
}

// round 14
// speedup vs baseline: 1.0498x; 1.0103x over previous
#include <cuda_runtime.h>
#include <cuda_bf16.h>
#include <math.h>
#include <stdint.h>

// Problem constants
#define BATCH 64
#define TT    1024
#define DIN   64
#define HID   128
#define G3    384   // 3*HID
#define D2    256   // 2*HID
#define MROWS (BATCH*TT)   // 65536

typedef unsigned long long ull;

// ---------------- f32x2 packed helpers (sm_103a FFMA2) ----------------------
__device__ __forceinline__ ull fma2(ull a, ull b, ull c) {
    ull d;
    asm("fma.rn.f32x2 %0, %1, %2, %3;" : "=l"(d) : "l"(a), "l"(b), "l"(c));
    return d;
}
__device__ __forceinline__ float2 unpack2(ull v) {
    float2 r;
    asm("mov.b64 {%0, %1}, %2;" : "=f"(r.x), "=f"(r.y) : "l"(v));
    return r;
}
__device__ __forceinline__ float sigm(float x) {
    return 1.f / (1.f + __expf(-x));
}
__device__ __forceinline__ float ftanh(float x) {
    return __fmaf_rn(2.f, 1.f / (1.f + __expf(-2.f * x)), -1.f);
}

// ---------------- bf16 HMMA (m16n8k16) --------------------------------------
__device__ __forceinline__ void mma_bf16(float* c,
                                         uint32_t a0, uint32_t a1, uint32_t a2, uint32_t a3,
                                         uint32_t b0, uint32_t b1) {
    asm volatile(
        "mma.sync.aligned.m16n8k16.row.col.f32.bf16.bf16.f32 "
        "{%0,%1,%2,%3}, {%4,%5,%6,%7}, {%8,%9}, {%0,%1,%2,%3};"
        : "+f"(c[0]), "+f"(c[1]), "+f"(c[2]), "+f"(c[3])
        : "r"(a0), "r"(a1), "r"(a2), "r"(a3), "r"(b0), "r"(b1));
}

// ---------------- scratch (device globals; no allocation allowed) ----------
__device__ float g_xW[2][MROWS][G3];          // input projections per dir
__device__ float g_z1[MROWS][D2];             // layer-1 output (fp32 for attn)
__device__ __nv_bfloat16 g_xh[MROWS * DIN],  g_xl[MROWS * DIN];
__device__ __nv_bfloat16 g_z0h[MROWS * D2],  g_z0l[MROWS * D2];
__device__ __nv_bfloat16 g_w0h[2][G3 * DIN], g_w0l[2][G3 * DIN];
__device__ __nv_bfloat16 g_w1h[2][G3 * D2],  g_w1l[2][G3 * D2];

// ---------------- fused fp32 -> bf16 (hi, lo) split conversion -------------
#define XN  (MROWS * DIN)
#define W0N (G3 * DIN)
#define W1N (G3 * D2)
__global__ __launch_bounds__(256)
void convert_all_kernel(const float* __restrict__ x,
                        const float* __restrict__ w0f, const float* __restrict__ w0b,
                        const float* __restrict__ w1f, const float* __restrict__ w1b)
{
    const int total = XN + 2 * W0N + 2 * W1N;
    for (int i = blockIdx.x * 256 + threadIdx.x; i < total; i += gridDim.x * 256) {
        const float* src;
        __nv_bfloat16 *hi, *lo;
        int k = i;
        if (k < XN)                    { src = x;   hi = g_xh;     lo = g_xl;     }
        else if ((k -= XN) < W0N)      { src = w0f; hi = g_w0h[0]; lo = g_w0l[0]; }
        else if ((k -= W0N) < W0N)     { src = w0b; hi = g_w0h[1]; lo = g_w0l[1]; }
        else if ((k -= W0N) < W1N)     { src = w1f; hi = g_w1h[0]; lo = g_w1l[0]; }
        else      { k -= W1N;            src = w1b; hi = g_w1h[1]; lo = g_w1l[1]; }
        float v = src[k];
        __nv_bfloat16 h = __float2bfloat16(v);
        hi[k] = h;
        lo[k] = __float2bfloat16(v - __bfloat162float(h));
    }
}

// ---------------- HMMA projection GEMM (R10 — measured best: 315us) --------
#define LDP 40
__global__ __launch_bounds__(256, 1)
void mma_proj_kernel(const float* __restrict__ bf,  const float* __restrict__ bb,
                     const float* __restrict__ bhf, const float* __restrict__ bhb,
                     int K, int layer)
{
    __shared__ __align__(16) __nv_bfloat16 sAh[128][LDP];
    __shared__ __align__(16) __nv_bfloat16 sAl[128][LDP];
    __shared__ __align__(16) __nv_bfloat16 sWh[128][LDP];
    __shared__ __align__(16) __nv_bfloat16 sWl[128][LDP];
    __shared__ float sBias[128];

    const int tid  = threadIdx.x;
    const int wid  = tid >> 5;
    const int lane = tid & 31;
    const int g    = lane >> 2;
    const int tig  = lane & 3;
    const int wr   = wid >> 1;
    const int wc   = wid & 1;
    const int m0   = blockIdx.x * 128;
    const int n0   = blockIdx.y * 128;
    const int dir  = blockIdx.z;

    const __nv_bfloat16* __restrict__ Ah = layer ? g_z0h : g_xh;
    const __nv_bfloat16* __restrict__ Al = layer ? g_z0l : g_xl;
    const __nv_bfloat16* __restrict__ Wh = layer ? g_w1h[dir] : g_w0h[dir];
    const __nv_bfloat16* __restrict__ Wl = layer ? g_w1l[dir] : g_w0l[dir];
    const float* __restrict__ bias = dir ? bb : bf;
    const float* __restrict__ bhh  = dir ? bhb : bhf;

    if (tid < 128) {
        int c = n0 + tid;
        sBias[tid] = bias[c] + (c < 2 * HID ? bhh[c] : 0.f);
    }

    const int lr0 = tid >> 1;
    const int lc0 = (tid & 1) * 16;

    float acc[2][8][4];
    #pragma unroll
    for (int a = 0; a < 2; ++a)
        #pragma unroll
        for (int b = 0; b < 8; ++b)
            #pragma unroll
            for (int cc = 0; cc < 4; ++cc) acc[a][b][cc] = 0.f;

    const int nchunks = K >> 5;

    uint4 pAh0, pAh1, pAl0, pAl1, pWh0, pWh1, pWl0, pWl1;
    {
        const size_t ga = (size_t)(m0 + lr0) * K + lc0;
        const size_t gw = (size_t)(n0 + lr0) * K + lc0;
        pAh0 = *(const uint4*)(Ah + ga);     pAh1 = *(const uint4*)(Ah + ga + 8);
        pAl0 = *(const uint4*)(Al + ga);     pAl1 = *(const uint4*)(Al + ga + 8);
        pWh0 = *(const uint4*)(Wh + gw);     pWh1 = *(const uint4*)(Wh + gw + 8);
        pWl0 = *(const uint4*)(Wl + gw);     pWl1 = *(const uint4*)(Wl + gw + 8);
    }

    for (int c = 0; c < nchunks; ++c) {
        *(uint4*)&sAh[lr0][lc0] = pAh0;  *(uint4*)&sAh[lr0][lc0 + 8] = pAh1;
        *(uint4*)&sAl[lr0][lc0] = pAl0;  *(uint4*)&sAl[lr0][lc0 + 8] = pAl1;
        *(uint4*)&sWh[lr0][lc0] = pWh0;  *(uint4*)&sWh[lr0][lc0 + 8] = pWh1;
        *(uint4*)&sWl[lr0][lc0] = pWl0;  *(uint4*)&sWl[lr0][lc0 + 8] = pWl1;
        __syncthreads();

        if (c + 1 < nchunks) {
            const size_t ga = (size_t)(m0 + lr0) * K + (c + 1) * 32 + lc0;
            const size_t gw = (size_t)(n0 + lr0) * K + (c + 1) * 32 + lc0;
            pAh0 = *(const uint4*)(Ah + ga);  pAh1 = *(const uint4*)(Ah + ga + 8);
            pAl0 = *(const uint4*)(Al + ga);  pAl1 = *(const uint4*)(Al + ga + 8);
            pWh0 = *(const uint4*)(Wh + gw);  pWh1 = *(const uint4*)(Wh + gw + 8);
            pWl0 = *(const uint4*)(Wl + gw);  pWl1 = *(const uint4*)(Wl + gw + 8);
        }

        #pragma unroll
        for (int ks = 0; ks < 2; ++ks) {
            const int kc = ks * 16 + tig * 2;
            uint32_t ah[2][4], al[2][4];
            #pragma unroll
            for (int mt = 0; mt < 2; ++mt) {
                const int r = wr * 32 + mt * 16 + g;
                ah[mt][0] = *(const uint32_t*)&sAh[r][kc];
                ah[mt][1] = *(const uint32_t*)&sAh[r + 8][kc];
                ah[mt][2] = *(const uint32_t*)&sAh[r][kc + 8];
                ah[mt][3] = *(const uint32_t*)&sAh[r + 8][kc + 8];
                al[mt][0] = *(const uint32_t*)&sAl[r][kc];
                al[mt][1] = *(const uint32_t*)&sAl[r + 8][kc];
                al[mt][2] = *(const uint32_t*)&sAl[r][kc + 8];
                al[mt][3] = *(const uint32_t*)&sAl[r + 8][kc + 8];
            }
            #pragma unroll
            for (int nt = 0; nt < 8; ++nt) {
                const int wn = wc * 64 + nt * 8 + g;
                uint32_t bh0 = *(const uint32_t*)&sWh[wn][kc];
                uint32_t bh1 = *(const uint32_t*)&sWh[wn][kc + 8];
                uint32_t bl0 = *(const uint32_t*)&sWl[wn][kc];
                uint32_t bl1 = *(const uint32_t*)&sWl[wn][kc + 8];
                #pragma unroll
                for (int mt = 0; mt < 2; ++mt) {
                    mma_bf16(acc[mt][nt], ah[mt][0], ah[mt][1], ah[mt][2], ah[mt][3], bh0, bh1);
                    mma_bf16(acc[mt][nt], ah[mt][0], ah[mt][1], ah[mt][2], ah[mt][3], bl0, bl1);
                    mma_bf16(acc[mt][nt], al[mt][0], al[mt][1], al[mt][2], al[mt][3], bh0, bh1);
                }
            }
        }
        __syncthreads();
    }

    float* Cout = &g_xW[dir][0][0];
    #pragma unroll
    for (int mt = 0; mt < 2; ++mt) {
        const int mrow = m0 + wr * 32 + mt * 16 + g;
        #pragma unroll
        for (int nt = 0; nt < 8; ++nt) {
            const int ncol  = wc * 64 + nt * 8 + tig * 2;
            const int gcol  = n0 + ncol;
            float2 o0 = {acc[mt][nt][0] + sBias[ncol],
                         acc[mt][nt][1] + sBias[ncol + 1]};
            float2 o1 = {acc[mt][nt][2] + sBias[ncol],
                         acc[mt][nt][3] + sBias[ncol + 1]};
            *(float2*)(Cout + (size_t)mrow * G3 + gcol)       = o0;
            *(float2*)(Cout + (size_t)(mrow + 8) * G3 + gcol) = o1;
        }
    }
}

// ---------------- GRU recurrence (R5/R8/R10 structure — converged) ---------
__global__ __launch_bounds__(384, 1)
void gru_scan_kernel(const float* __restrict__ whh_f, const float* __restrict__ whh_b,
                     const float* __restrict__ bhh_f, const float* __restrict__ bhh_b,
                     int layer)
{
    const int b   = blockIdx.x >> 1;
    const int dir = blockIdx.x & 1;
    const int j   = threadIdx.x;                 // 0..383 = gate row

    const float* __restrict__ whh = dir ? whh_b : whh_f;
    const float* __restrict__ bhh = dir ? bhh_b : bhh_f;

    __shared__ __align__(16) float h_s[HID];
    __shared__ float rz_s[2 * HID];

    ull w2[64];
    #pragma unroll
    for (int i = 0; i < 64; i += 2) {
        ulonglong2 v = *(const ulonglong2*)(whh + (size_t)j * HID + 2 * i);
        w2[i] = v.x; w2[i + 1] = v.y;
    }
    const bool is_n = (j >= 2 * HID);
    const int  o    = j - 2 * HID;
    const float bj  = is_n ? bhh[j] : 0.f;       // bhh_n stays inside r*(.)
    float hreg = 0.f;
    if (j < HID) h_s[j] = 0.f;

    const float* __restrict__ gi = &g_xW[dir][(size_t)b * TT][0];
    float* __restrict__ zf = &g_z1[(size_t)b * TT][0] + dir * HID;
    __nv_bfloat16* __restrict__ zh = g_z0h + (size_t)b * TT * D2 + dir * HID;
    __nv_bfloat16* __restrict__ zl = g_z0l + (size_t)b * TT * D2 + dir * HID;

    const int t0 = dir ? (TT - 1) : 0;
    float gi_v = __ldcs(gi + (size_t)t0 * G3 + j);
    __syncthreads();

    for (int t = 0; t < TT; ++t) {
        const int tt = dir ? (TT - 1 - t) : t;

        float pre = 0.f;
        if (t + 1 < TT) {
            const int tn = dir ? (TT - 2 - t) : (t + 1);
            pre = __ldcs(gi + (size_t)tn * G3 + j);
        }

        ull a0 = 0ull, a1 = 0ull;
        const ull* h2 = (const ull*)h_s;
        #pragma unroll
        for (int i = 0; i < 64; i += 8) {
            ulonglong2 hv0 = *(const ulonglong2*)(h2 + i);
            ulonglong2 hv1 = *(const ulonglong2*)(h2 + i + 2);
            ulonglong2 hv2 = *(const ulonglong2*)(h2 + i + 4);
            ulonglong2 hv3 = *(const ulonglong2*)(h2 + i + 6);
            a0 = fma2(w2[i],     hv0.x, a0);
            a1 = fma2(w2[i + 1], hv0.y, a1);
            a0 = fma2(w2[i + 2], hv1.x, a0);
            a1 = fma2(w2[i + 3], hv1.y, a1);
            a0 = fma2(w2[i + 4], hv2.x, a0);
            a1 = fma2(w2[i + 5], hv2.y, a1);
            a0 = fma2(w2[i + 6], hv3.x, a0);
            a1 = fma2(w2[i + 7], hv3.y, a1);
        }
        float2 s0 = unpack2(a0), s1 = unpack2(a1);
        float gh = (s0.x + s0.y) + (s1.x + s1.y);

        if (!is_n) rz_s[j] = sigm(gi_v + gh);
        __syncthreads();

        if (is_n) {
            float r  = rz_s[o];
            float zg = rz_s[HID + o];
            float n  = ftanh(gi_v + r * (gh + bj));
            hreg = (1.f - zg) * n + zg * hreg;
            h_s[o] = hreg;
            if (layer) {
                zf[(size_t)tt * D2 + o] = hreg;
            } else {
                __nv_bfloat16 hi = __float2bfloat16(hreg);
                zh[(size_t)tt * D2 + o] = hi;
                zl[(size_t)tt * D2 + o] = __float2bfloat16(hreg - __bfloat162float(hi));
            }
        }
        gi_v = pre;
        __syncthreads();
    }
}

// ---------------- attention pooling + heads (R10 — proven) -----------------
__global__ __launch_bounds__(256)
void attn_head_kernel(const float* __restrict__ attn_w, const float* __restrict__ attn_b,
                      const float* __restrict__ motor_w, const float* __restrict__ motor_b,
                      const float* __restrict__ state_w, const float* __restrict__ state_b,
                      const int* __restrict__ motor_k, float* __restrict__ out)
{
    const int b = blockIdx.x;
    const int tid = threadIdx.x;       // 256 threads
    const int warp = tid >> 5, lane = tid & 31;

    __shared__ float sw[D2];
    __shared__ float sc[TT];
    __shared__ float red[256];
    __shared__ float pooled[D2];

    sw[tid] = attn_w[tid];
    __syncthreads();

    const float* __restrict__ zb = &g_z1[(size_t)b * TT][0];
    const float ab = attn_b[0];

    for (int t = warp; t < TT; t += 8) {
        const float* zt = zb + (size_t)t * D2;
        float s = 0.f;
        #pragma unroll
        for (int d = lane; d < D2; d += 32) s += zt[d] * sw[d];
        #pragma unroll
        for (int o = 16; o; o >>= 1) s += __shfl_xor_sync(0xffffffffu, s, o);
        if (lane == 0) sc[t] = s + ab;
    }
    __syncthreads();

    float m = -INFINITY;
    for (int t = tid; t < TT; t += 256) m = fmaxf(m, sc[t]);
    red[tid] = m; __syncthreads();
    for (int s = 128; s; s >>= 1) {
        if (tid < s) red[tid] = fmaxf(red[tid], red[tid + s]);
        __syncthreads();
    }
    m = red[0]; __syncthreads();

    float sum = 0.f;
    for (int t = tid; t < TT; t += 256) {
        float e = __expf(sc[t] - m);
        sc[t] = e;
        sum += e;
    }
    red[tid] = sum; __syncthreads();
    for (int s = 128; s; s >>= 1) {
        if (tid < s) red[tid] += red[tid + s];
        __syncthreads();
    }
    const float inv = 1.f / red[0];
    __syncthreads();

    float acc = 0.f;
    #pragma unroll 8
    for (int t = 0; t < TT; ++t) acc += sc[t] * zb[(size_t)t * D2 + tid];
    pooled[tid] = acc * inv;
    __syncthreads();

    if (warp < 7) {
        const float* wv;
        float bv;
        int mk = motor_k[b];
        if (warp < 5) { wv = motor_w + warp * D2;              bv = motor_b[warp]; }
        else          { int c = warp - 5;
                        wv = state_w + (size_t)(mk * 2 + c) * D2;
                        bv = state_b[mk * 2 + c]; }
        float s = 0.f;
        #pragma unroll
        for (int d = lane; d < D2; d += 32) s += pooled[d] * wv[d];
        #pragma unroll
        for (int o = 16; o; o >>= 1) s += __shfl_xor_sync(0xffffffffu, s, o);
        if (lane == 0) {
            if (warp < 5) out[b * 5 + warp] = s + bv;
            else          out[BATCH * 5 + b * 2 + (warp - 5)] = s + bv;
        }
    }
}

// ---------------- launch ----------------------------------------------------
extern "C" void kernel_launch(void* const* d_in, const int* in_sizes, int n_in,
                              void* d_out, int out_size)
{
    const float* x        = (const float*)d_in[0];
    const int*   motor_k  = (const int*)  d_in[1];
    const float* wih_l0f  = (const float*)d_in[2];
    const float* whh_l0f  = (const float*)d_in[3];
    const float* bih_l0f  = (const float*)d_in[4];
    const float* bhh_l0f  = (const float*)d_in[5];
    const float* wih_l0b  = (const float*)d_in[6];
    const float* whh_l0b  = (const float*)d_in[7];
    const float* bih_l0b  = (const float*)d_in[8];
    const float* bhh_l0b  = (const float*)d_in[9];
    const float* wih_l1f  = (const float*)d_in[10];
    const float* whh_l1f  = (const float*)d_in[11];
    const float* bih_l1f  = (const float*)d_in[12];
    const float* bhh_l1f  = (const float*)d_in[13];
    const float* wih_l1b  = (const float*)d_in[14];
    const float* whh_l1b  = (const float*)d_in[15];
    const float* bih_l1b  = (const float*)d_in[16];
    const float* bhh_l1b  = (const float*)d_in[17];
    const float* attn_w   = (const float*)d_in[18];
    const float* attn_b   = (const float*)d_in[19];
    const float* motor_w  = (const float*)d_in[20];
    const float* motor_b  = (const float*)d_in[21];
    const float* state_w  = (const float*)d_in[22];
    const float* state_b  = (const float*)d_in[23];
    float* out = (float*)d_out;

    // single fused bf16 (hi,lo) conversion pass
    convert_all_kernel<<<2368, 256>>>(x, wih_l0f, wih_l0b, wih_l1f, wih_l1b);

    dim3 gproj(MROWS / 128, G3 / 128, 2);   // 512 x 3 x 2

    // layer 0
    mma_proj_kernel<<<gproj, 256>>>(bih_l0f, bih_l0b, bhh_l0f, bhh_l0b, DIN, 0);
    gru_scan_kernel<<<BATCH * 2, 384>>>(whh_l0f, whh_l0b, bhh_l0f, bhh_l0b, 0);
    // layer 1
    mma_proj_kernel<<<gproj, 256>>>(bih_l1f, bih_l1b, bhh_l1f, bhh_l1b, D2, 1);
    gru_scan_kernel<<<BATCH * 2, 384>>>(whh_l1f, whh_l1b, bhh_l1f, bhh_l1b, 1);
    // pooling + heads
    attn_head_kernel<<<BATCH, 256>>>(attn_w, attn_b, motor_w, motor_b,
                                     state_w, state_b, motor_k, out);
}

// round 15
// speedup vs baseline: 1.0903x; 1.0386x over previous
#include <cuda_runtime.h>
#include <cuda_bf16.h>
#include <math.h>
#include <stdint.h>

// Problem constants
#define BATCH 64
#define TT    1024
#define DIN   64
#define HID   128
#define G3    384   // 3*HID
#define D2    256   // 2*HID
#define MROWS (BATCH*TT)   // 65536

typedef unsigned long long ull;

// ---------------- f32x2 packed helpers (sm_103a FFMA2) ----------------------
__device__ __forceinline__ ull fma2(ull a, ull b, ull c) {
    ull d;
    asm("fma.rn.f32x2 %0, %1, %2, %3;" : "=l"(d) : "l"(a), "l"(b), "l"(c));
    return d;
}
__device__ __forceinline__ float2 unpack2(ull v) {
    float2 r;
    asm("mov.b64 {%0, %1}, %2;" : "=f"(r.x), "=f"(r.y) : "l"(v));
    return r;
}
__device__ __forceinline__ float sigm(float x) {
    return 1.f / (1.f + __expf(-x));
}
__device__ __forceinline__ float ftanh(float x) {
    return __fmaf_rn(2.f, 1.f / (1.f + __expf(-2.f * x)), -1.f);
}

// ---------------- bf16 HMMA (m16n8k16) --------------------------------------
__device__ __forceinline__ void mma_bf16(float* c,
                                         uint32_t a0, uint32_t a1, uint32_t a2, uint32_t a3,
                                         uint32_t b0, uint32_t b1) {
    asm volatile(
        "mma.sync.aligned.m16n8k16.row.col.f32.bf16.bf16.f32 "
        "{%0,%1,%2,%3}, {%4,%5,%6,%7}, {%8,%9}, {%0,%1,%2,%3};"
        : "+f"(c[0]), "+f"(c[1]), "+f"(c[2]), "+f"(c[3])
        : "r"(a0), "r"(a1), "r"(a2), "r"(a3), "r"(b0), "r"(b1));
}

// ---------------- scratch (device globals; no allocation allowed) ----------
__device__ float g_xW[2][MROWS][G3];          // input projections per dir
__device__ float g_z1[MROWS][D2];             // layer-1 output (fp32 for attn)
__device__ __nv_bfloat16 g_xh[MROWS * DIN],  g_xl[MROWS * DIN];
__device__ __nv_bfloat16 g_z0h[MROWS * D2],  g_z0l[MROWS * D2];
__device__ __nv_bfloat16 g_w0h[2][G3 * DIN], g_w0l[2][G3 * DIN];
__device__ __nv_bfloat16 g_w1h[2][G3 * D2],  g_w1l[2][G3 * D2];
__device__ float g_sc[BATCH][TT];             // attn scores -> weights
__device__ float g_pool[BATCH][D2];           // pooled vectors

// ---------------- fused fp32 -> bf16 (hi, lo) split conversion -------------
#define XN  (MROWS * DIN)
#define W0N (G3 * DIN)
#define W1N (G3 * D2)
__global__ __launch_bounds__(256)
void convert_all_kernel(const float* __restrict__ x,
                        const float* __restrict__ w0f, const float* __restrict__ w0b,
                        const float* __restrict__ w1f, const float* __restrict__ w1b)
{
    const int total = XN + 2 * W0N + 2 * W1N;
    for (int i = blockIdx.x * 256 + threadIdx.x; i < total; i += gridDim.x * 256) {
        const float* src;
        __nv_bfloat16 *hi, *lo;
        int k = i;
        if (k < XN)                    { src = x;   hi = g_xh;     lo = g_xl;     }
        else if ((k -= XN) < W0N)      { src = w0f; hi = g_w0h[0]; lo = g_w0l[0]; }
        else if ((k -= W0N) < W0N)     { src = w0b; hi = g_w0h[1]; lo = g_w0l[1]; }
        else if ((k -= W0N) < W1N)     { src = w1f; hi = g_w1h[0]; lo = g_w1l[0]; }
        else      { k -= W1N;            src = w1b; hi = g_w1h[1]; lo = g_w1l[1]; }
        float v = src[k];
        __nv_bfloat16 h = __float2bfloat16(v);
        hi[k] = h;
        lo[k] = __float2bfloat16(v - __bfloat162float(h));
    }
}

// ---------------- HMMA projection GEMM (R10 — measured best) ---------------
#define LDP 40
__global__ __launch_bounds__(256, 1)
void mma_proj_kernel(const float* __restrict__ bf,  const float* __restrict__ bb,
                     const float* __restrict__ bhf, const float* __restrict__ bhb,
                     int K, int layer)
{
    __shared__ __align__(16) __nv_bfloat16 sAh[128][LDP];
    __shared__ __align__(16) __nv_bfloat16 sAl[128][LDP];
    __shared__ __align__(16) __nv_bfloat16 sWh[128][LDP];
    __shared__ __align__(16) __nv_bfloat16 sWl[128][LDP];
    __shared__ float sBias[128];

    const int tid  = threadIdx.x;
    const int wid  = tid >> 5;
    const int lane = tid & 31;
    const int g    = lane >> 2;
    const int tig  = lane & 3;
    const int wr   = wid >> 1;
    const int wc   = wid & 1;
    const int m0   = blockIdx.x * 128;
    const int n0   = blockIdx.y * 128;
    const int dir  = blockIdx.z;

    const __nv_bfloat16* __restrict__ Ah = layer ? g_z0h : g_xh;
    const __nv_bfloat16* __restrict__ Al = layer ? g_z0l : g_xl;
    const __nv_bfloat16* __restrict__ Wh = layer ? g_w1h[dir] : g_w0h[dir];
    const __nv_bfloat16* __restrict__ Wl = layer ? g_w1l[dir] : g_w0l[dir];
    const float* __restrict__ bias = dir ? bb : bf;
    const float* __restrict__ bhh  = dir ? bhb : bhf;

    if (tid < 128) {
        int c = n0 + tid;
        sBias[tid] = bias[c] + (c < 2 * HID ? bhh[c] : 0.f);
    }

    const int lr0 = tid >> 1;
    const int lc0 = (tid & 1) * 16;

    float acc[2][8][4];
    #pragma unroll
    for (int a = 0; a < 2; ++a)
        #pragma unroll
        for (int b = 0; b < 8; ++b)
            #pragma unroll
            for (int cc = 0; cc < 4; ++cc) acc[a][b][cc] = 0.f;

    const int nchunks = K >> 5;

    uint4 pAh0, pAh1, pAl0, pAl1, pWh0, pWh1, pWl0, pWl1;
    {
        const size_t ga = (size_t)(m0 + lr0) * K + lc0;
        const size_t gw = (size_t)(n0 + lr0) * K + lc0;
        pAh0 = *(const uint4*)(Ah + ga);     pAh1 = *(const uint4*)(Ah + ga + 8);
        pAl0 = *(const uint4*)(Al + ga);     pAl1 = *(const uint4*)(Al + ga + 8);
        pWh0 = *(const uint4*)(Wh + gw);     pWh1 = *(const uint4*)(Wh + gw + 8);
        pWl0 = *(const uint4*)(Wl + gw);     pWl1 = *(const uint4*)(Wl + gw + 8);
    }

    for (int c = 0; c < nchunks; ++c) {
        *(uint4*)&sAh[lr0][lc0] = pAh0;  *(uint4*)&sAh[lr0][lc0 + 8] = pAh1;
        *(uint4*)&sAl[lr0][lc0] = pAl0;  *(uint4*)&sAl[lr0][lc0 + 8] = pAl1;
        *(uint4*)&sWh[lr0][lc0] = pWh0;  *(uint4*)&sWh[lr0][lc0 + 8] = pWh1;
        *(uint4*)&sWl[lr0][lc0] = pWl0;  *(uint4*)&sWl[lr0][lc0 + 8] = pWl1;
        __syncthreads();

        if (c + 1 < nchunks) {
            const size_t ga = (size_t)(m0 + lr0) * K + (c + 1) * 32 + lc0;
            const size_t gw = (size_t)(n0 + lr0) * K + (c + 1) * 32 + lc0;
            pAh0 = *(const uint4*)(Ah + ga);  pAh1 = *(const uint4*)(Ah + ga + 8);
            pAl0 = *(const uint4*)(Al + ga);  pAl1 = *(const uint4*)(Al + ga + 8);
            pWh0 = *(const uint4*)(Wh + gw);  pWh1 = *(const uint4*)(Wh + gw + 8);
            pWl0 = *(const uint4*)(Wl + gw);  pWl1 = *(const uint4*)(Wl + gw + 8);
        }

        #pragma unroll
        for (int ks = 0; ks < 2; ++ks) {
            const int kc = ks * 16 + tig * 2;
            uint32_t ah[2][4], al[2][4];
            #pragma unroll
            for (int mt = 0; mt < 2; ++mt) {
                const int r = wr * 32 + mt * 16 + g;
                ah[mt][0] = *(const uint32_t*)&sAh[r][kc];
                ah[mt][1] = *(const uint32_t*)&sAh[r + 8][kc];
                ah[mt][2] = *(const uint32_t*)&sAh[r][kc + 8];
                ah[mt][3] = *(const uint32_t*)&sAh[r + 8][kc + 8];
                al[mt][0] = *(const uint32_t*)&sAl[r][kc];
                al[mt][1] = *(const uint32_t*)&sAl[r + 8][kc];
                al[mt][2] = *(const uint32_t*)&sAl[r][kc + 8];
                al[mt][3] = *(const uint32_t*)&sAl[r + 8][kc + 8];
            }
            #pragma unroll
            for (int nt = 0; nt < 8; ++nt) {
                const int wn = wc * 64 + nt * 8 + g;
                uint32_t bh0 = *(const uint32_t*)&sWh[wn][kc];
                uint32_t bh1 = *(const uint32_t*)&sWh[wn][kc + 8];
                uint32_t bl0 = *(const uint32_t*)&sWl[wn][kc];
                uint32_t bl1 = *(const uint32_t*)&sWl[wn][kc + 8];
                #pragma unroll
                for (int mt = 0; mt < 2; ++mt) {
                    mma_bf16(acc[mt][nt], ah[mt][0], ah[mt][1], ah[mt][2], ah[mt][3], bh0, bh1);
                    mma_bf16(acc[mt][nt], ah[mt][0], ah[mt][1], ah[mt][2], ah[mt][3], bl0, bl1);
                    mma_bf16(acc[mt][nt], al[mt][0], al[mt][1], al[mt][2], al[mt][3], bh0, bh1);
                }
            }
        }
        __syncthreads();
    }

    float* Cout = &g_xW[dir][0][0];
    #pragma unroll
    for (int mt = 0; mt < 2; ++mt) {
        const int mrow = m0 + wr * 32 + mt * 16 + g;
        #pragma unroll
        for (int nt = 0; nt < 8; ++nt) {
            const int ncol  = wc * 64 + nt * 8 + tig * 2;
            const int gcol  = n0 + ncol;
            float2 o0 = {acc[mt][nt][0] + sBias[ncol],
                         acc[mt][nt][1] + sBias[ncol + 1]};
            float2 o1 = {acc[mt][nt][2] + sBias[ncol],
                         acc[mt][nt][3] + sBias[ncol + 1]};
            *(float2*)(Cout + (size_t)mrow * G3 + gcol)       = o0;
            *(float2*)(Cout + (size_t)(mrow + 8) * G3 + gcol) = o1;
        }
    }
}

// ---------------- GRU recurrence (R5/R8/R10 structure — converged) ---------
__global__ __launch_bounds__(384, 1)
void gru_scan_kernel(const float* __restrict__ whh_f, const float* __restrict__ whh_b,
                     const float* __restrict__ bhh_f, const float* __restrict__ bhh_b,
                     int layer)
{
    const int b   = blockIdx.x >> 1;
    const int dir = blockIdx.x & 1;
    const int j   = threadIdx.x;                 // 0..383 = gate row

    const float* __restrict__ whh = dir ? whh_b : whh_f;
    const float* __restrict__ bhh = dir ? bhh_b : bhh_f;

    __shared__ __align__(16) float h_s[HID];
    __shared__ float rz_s[2 * HID];

    ull w2[64];
    #pragma unroll
    for (int i = 0; i < 64; i += 2) {
        ulonglong2 v = *(const ulonglong2*)(whh + (size_t)j * HID + 2 * i);
        w2[i] = v.x; w2[i + 1] = v.y;
    }
    const bool is_n = (j >= 2 * HID);
    const int  o    = j - 2 * HID;
    const float bj  = is_n ? bhh[j] : 0.f;       // bhh_n stays inside r*(.)
    float hreg = 0.f;
    if (j < HID) h_s[j] = 0.f;

    const float* __restrict__ gi = &g_xW[dir][(size_t)b * TT][0];
    float* __restrict__ zf = &g_z1[(size_t)b * TT][0] + dir * HID;
    __nv_bfloat16* __restrict__ zh = g_z0h + (size_t)b * TT * D2 + dir * HID;
    __nv_bfloat16* __restrict__ zl = g_z0l + (size_t)b * TT * D2 + dir * HID;

    const int t0 = dir ? (TT - 1) : 0;
    float gi_v = __ldcs(gi + (size_t)t0 * G3 + j);
    __syncthreads();

    for (int t = 0; t < TT; ++t) {
        const int tt = dir ? (TT - 1 - t) : t;

        float pre = 0.f;
        if (t + 1 < TT) {
            const int tn = dir ? (TT - 2 - t) : (t + 1);
            pre = __ldcs(gi + (size_t)tn * G3 + j);
        }

        ull a0 = 0ull, a1 = 0ull;
        const ull* h2 = (const ull*)h_s;
        #pragma unroll
        for (int i = 0; i < 64; i += 8) {
            ulonglong2 hv0 = *(const ulonglong2*)(h2 + i);
            ulonglong2 hv1 = *(const ulonglong2*)(h2 + i + 2);
            ulonglong2 hv2 = *(const ulonglong2*)(h2 + i + 4);
            ulonglong2 hv3 = *(const ulonglong2*)(h2 + i + 6);
            a0 = fma2(w2[i],     hv0.x, a0);
            a1 = fma2(w2[i + 1], hv0.y, a1);
            a0 = fma2(w2[i + 2], hv1.x, a0);
            a1 = fma2(w2[i + 3], hv1.y, a1);
            a0 = fma2(w2[i + 4], hv2.x, a0);
            a1 = fma2(w2[i + 5], hv2.y, a1);
            a0 = fma2(w2[i + 6], hv3.x, a0);
            a1 = fma2(w2[i + 7], hv3.y, a1);
        }
        float2 s0 = unpack2(a0), s1 = unpack2(a1);
        float gh = (s0.x + s0.y) + (s1.x + s1.y);

        if (!is_n) rz_s[j] = sigm(gi_v + gh);
        __syncthreads();

        if (is_n) {
            float r  = rz_s[o];
            float zg = rz_s[HID + o];
            float n  = ftanh(gi_v + r * (gh + bj));
            hreg = (1.f - zg) * n + zg * hreg;
            h_s[o] = hreg;
            if (layer) {
                zf[(size_t)tt * D2 + o] = hreg;
            } else {
                __nv_bfloat16 hi = __float2bfloat16(hreg);
                zh[(size_t)tt * D2 + o] = hi;
                zl[(size_t)tt * D2 + o] = __float2bfloat16(hreg - __bfloat162float(hi));
            }
        }
        gi_v = pre;
        __syncthreads();
    }
}

// ---------------- attention: scores (wide) ----------------------------------
// grid (BATCH, 8): CTA computes scores for 128 timesteps; warp per t.
__global__ __launch_bounds__(256)
void attn_scores_kernel(const float* __restrict__ attn_w,
                        const float* __restrict__ attn_b)
{
    const int b   = blockIdx.x;
    const int tc  = blockIdx.y;
    const int tid = threadIdx.x;
    const int warp = tid >> 5, lane = tid & 31;

    __shared__ float sw[D2];
    if (tid < D2) sw[tid] = attn_w[tid];
    __syncthreads();

    const float ab = attn_b[0];
    const float* __restrict__ zb = &g_z1[(size_t)b * TT][0];

    for (int t = tc * 128 + warp; t < tc * 128 + 128; t += 8) {
        const float* zt = zb + (size_t)t * D2;
        float s = 0.f;
        #pragma unroll
        for (int d = lane; d < D2; d += 32) s += zt[d] * sw[d];
        #pragma unroll
        for (int o = 16; o; o >>= 1) s += __shfl_xor_sync(0xffffffffu, s, o);
        if (lane == 0) g_sc[b][t] = s + ab;
    }
}

// ---------------- attention: per-batch softmax + zero pool ------------------
__global__ __launch_bounds__(256)
void attn_softmax_kernel()
{
    const int b   = blockIdx.x;
    const int tid = threadIdx.x;
    __shared__ float red[256];

    g_pool[b][tid] = 0.f;   // zero pooled accumulator (256 = D2)

    float m = -INFINITY;
    for (int t = tid; t < TT; t += 256) m = fmaxf(m, g_sc[b][t]);
    red[tid] = m; __syncthreads();
    for (int s = 128; s; s >>= 1) {
        if (tid < s) red[tid] = fmaxf(red[tid], red[tid + s]);
        __syncthreads();
    }
    m = red[0]; __syncthreads();

    float sum = 0.f;
    float e0 = __expf(g_sc[b][tid] - m);
    float e1 = __expf(g_sc[b][tid + 256] - m);
    float e2 = __expf(g_sc[b][tid + 512] - m);
    float e3 = __expf(g_sc[b][tid + 768] - m);
    sum = (e0 + e1) + (e2 + e3);
    red[tid] = sum; __syncthreads();
    for (int s = 128; s; s >>= 1) {
        if (tid < s) red[tid] += red[tid + s];
        __syncthreads();
    }
    const float inv = 1.f / red[0];

    g_sc[b][tid]       = e0 * inv;
    g_sc[b][tid + 256] = e1 * inv;
    g_sc[b][tid + 512] = e2 * inv;
    g_sc[b][tid + 768] = e3 * inv;
}

// ---------------- attention: pooled partials --------------------------------
// grid (BATCH, 4): CTA accumulates 256 timesteps for all 256 dims.
__global__ __launch_bounds__(256)
void attn_pool_kernel()
{
    const int b   = blockIdx.x;
    const int tq  = blockIdx.y;
    const int tid = threadIdx.x;            // = d

    __shared__ float sa[256];
    sa[tid] = g_sc[b][tq * 256 + tid];
    __syncthreads();

    const float* __restrict__ zb = &g_z1[(size_t)b * TT + tq * 256][0];
    float acc = 0.f;
    #pragma unroll 8
    for (int t = 0; t < 256; ++t)
        acc += sa[t] * zb[(size_t)t * D2 + tid];
    atomicAdd(&g_pool[b][tid], acc);
}

// ---------------- attention: heads ------------------------------------------
__global__ __launch_bounds__(224)
void attn_heads_kernel(const float* __restrict__ motor_w, const float* __restrict__ motor_b,
                       const float* __restrict__ state_w, const float* __restrict__ state_b,
                       const int* __restrict__ motor_k, float* __restrict__ out)
{
    const int b    = blockIdx.x;
    const int tid  = threadIdx.x;           // 224 = 7 warps
    const int warp = tid >> 5, lane = tid & 31;

    __shared__ float pooled[D2];
    if (tid < D2 - 0 && tid < 224) {        // 224 threads cover 224; finish with strided
    }
    for (int d = tid; d < D2; d += 224) pooled[d] = g_pool[b][d];
    __syncthreads();

    const float* wv;
    float bv;
    int mk = motor_k[b];
    if (warp < 5) { wv = motor_w + warp * D2;              bv = motor_b[warp]; }
    else          { int c = warp - 5;
                    wv = state_w + (size_t)(mk * 2 + c) * D2;
                    bv = state_b[mk * 2 + c]; }
    float s = 0.f;
    #pragma unroll
    for (int d = lane; d < D2; d += 32) s += pooled[d] * wv[d];
    #pragma unroll
    for (int o = 16; o; o >>= 1) s += __shfl_xor_sync(0xffffffffu, s, o);
    if (lane == 0) {
        if (warp < 5) out[b * 5 + warp] = s + bv;
        else          out[BATCH * 5 + b * 2 + (warp - 5)] = s + bv;
    }
}

// ---------------- launch ----------------------------------------------------
extern "C" void kernel_launch(void* const* d_in, const int* in_sizes, int n_in,
                              void* d_out, int out_size)
{
    const float* x        = (const float*)d_in[0];
    const int*   motor_k  = (const int*)  d_in[1];
    const float* wih_l0f  = (const float*)d_in[2];
    const float* whh_l0f  = (const float*)d_in[3];
    const float* bih_l0f  = (const float*)d_in[4];
    const float* bhh_l0f  = (const float*)d_in[5];
    const float* wih_l0b  = (const float*)d_in[6];
    const float* whh_l0b  = (const float*)d_in[7];
    const float* bih_l0b  = (const float*)d_in[8];
    const float* bhh_l0b  = (const float*)d_in[9];
    const float* wih_l1f  = (const float*)d_in[10];
    const float* whh_l1f  = (const float*)d_in[11];
    const float* bih_l1f  = (const float*)d_in[12];
    const float* bhh_l1f  = (const float*)d_in[13];
    const float* wih_l1b  = (const float*)d_in[14];
    const float* whh_l1b  = (const float*)d_in[15];
    const float* bih_l1b  = (const float*)d_in[16];
    const float* bhh_l1b  = (const float*)d_in[17];
    const float* attn_w   = (const float*)d_in[18];
    const float* attn_b   = (const float*)d_in[19];
    const float* motor_w  = (const float*)d_in[20];
    const float* motor_b  = (const float*)d_in[21];
    const float* state_w  = (const float*)d_in[22];
    const float* state_b  = (const float*)d_in[23];
    float* out = (float*)d_out;

    // single fused bf16 (hi,lo) conversion pass
    convert_all_kernel<<<2368, 256>>>(x, wih_l0f, wih_l0b, wih_l1f, wih_l1b);

    dim3 gproj(MROWS / 128, G3 / 128, 2);   // 512 x 3 x 2

    // layer 0
    mma_proj_kernel<<<gproj, 256>>>(bih_l0f, bih_l0b, bhh_l0f, bhh_l0b, DIN, 0);
    gru_scan_kernel<<<BATCH * 2, 384>>>(whh_l0f, whh_l0b, bhh_l0f, bhh_l0b, 0);
    // layer 1
    mma_proj_kernel<<<gproj, 256>>>(bih_l1f, bih_l1b, bhh_l1f, bhh_l1b, D2, 1);
    gru_scan_kernel<<<BATCH * 2, 384>>>(whh_l1f, whh_l1b, bhh_l1f, bhh_l1b, 1);

    // attention pipeline (wide)
    attn_scores_kernel<<<dim3(BATCH, 8), 256>>>(attn_w, attn_b);
    attn_softmax_kernel<<<BATCH, 256>>>();
    attn_pool_kernel<<<dim3(BATCH, 4), 256>>>();
    attn_heads_kernel<<<BATCH, 224>>>(motor_w, motor_b, state_w, state_b,
                                      motor_k, out);
}